// round 2
// baseline (speedup 1.0000x reference)
#include <cuda_runtime.h>
#include <math.h>

// ---------------- problem constants ----------------
#define NP 16384            // H*W per batch
#define NB 2                // batch
#define PL (NB * NP)        // floats per channel across batch

// scratch layout (channel counts)
// F 192 | X1 192 | MT 192 | OUTD 384 | ATTIN 192 | QKV0 576 | QKV 576 |
// OUTA 192 | XMID 192 | X2L 192 | FM 576 | XIN 1152 | DW 1152 | MT2 576 |
// OUT2 1152 | GX 576   => 8064 channels
#define OFF_F      ((size_t)0)
#define OFF_X1     (OFF_F     + (size_t)192  * PL)
#define OFF_MT     (OFF_X1    + (size_t)192  * PL)
#define OFF_OUTD   (OFF_MT    + (size_t)192  * PL)
#define OFF_ATTIN  (OFF_OUTD  + (size_t)384  * PL)
#define OFF_QKV0   (OFF_ATTIN + (size_t)192  * PL)
#define OFF_QKV    (OFF_QKV0  + (size_t)576  * PL)
#define OFF_OUTA   (OFF_QKV   + (size_t)576  * PL)
#define OFF_XMID   (OFF_OUTA  + (size_t)192  * PL)
#define OFF_X2L    (OFF_XMID  + (size_t)192  * PL)
#define OFF_FM     (OFF_X2L   + (size_t)192  * PL)
#define OFF_XIN    (OFF_FM    + (size_t)576  * PL)
#define OFF_DW     (OFF_XIN   + (size_t)1152 * PL)
#define OFF_MT2    (OFF_DW    + (size_t)1152 * PL)
#define OFF_OUT2   (OFF_MT2   + (size_t)576  * PL)
#define OFF_GX     (OFF_OUT2  + (size_t)1152 * PL)
#define OFF_NRM    (OFF_GX    + (size_t)576  * PL)   // 768 floats
#define OFF_S      (OFF_NRM   + (size_t)1024)        // 16 * 12288 partials
#define KSPLIT 16
#define SCRATCH_FLOATS (OFF_S + (size_t)KSPLIT * 12288)

__device__ float g_scratch[SCRATCH_FLOATS];

// ---------------- LayerNorm over channel dim ----------------
__global__ void ln_kernel(const float* __restrict__ in, const float* __restrict__ g,
                          const float* __restrict__ be, float* __restrict__ out, int C)
{
    int b = blockIdx.y;
    int p = blockIdx.x * 256 + threadIdx.x;
    const float* ib = in + (size_t)b * C * NP + p;
    float s = 0.f, ss = 0.f;
    for (int c = 0; c < C; c++) {
        float v = ib[(size_t)c * NP];
        s += v; ss += v * v;
    }
    float mu = s / C;
    float var = ss / C - mu * mu;
    float rstd = rsqrtf(var + 1e-5f);
    float* ob = out + (size_t)b * C * NP + p;
    for (int c = 0; c < C; c++) {
        float v = ib[(size_t)c * NP];
        ob[(size_t)c * NP] = (v - mu) * rstd * g[c] + be[c];
    }
}

// ---------------- unified GEMM: Y[o,p] = sum_k W[o,k] * Acat[k,p], + epilogue ----
// Acat rows: [0,K1) from A1, [K1,K) from A2.
// mode 0: Y = g
// mode 1: Y = g + E1[o,p]
// mode 2: base = (o<Chalf ? E1[o] : E2[o-Chalf]); Y = g*base + base
// mode 3: Y = gelu(E2[o,p]) * (g + E1[o,p])
#define BM 128
#define BN 128
#define BKK 8
__global__ void __launch_bounds__(256, 2)
gemm_kernel(const float* __restrict__ W, int K,
            const float* __restrict__ A1, int K1, int sA1,
            const float* __restrict__ A2, int sA2,
            int Cout,
            const float* __restrict__ E1, int sE1,
            const float* __restrict__ E2, int sE2,
            float* __restrict__ Y, int sY,
            int mode, int Chalf)
{
    __shared__ float As[BKK][BM];
    __shared__ float Bs[BKK][BN];
    int b  = blockIdx.z;
    int p0 = blockIdx.x * BN;
    int o0 = blockIdx.y * BM;
    const float* A1b = A1 + (size_t)b * sA1 * NP;
    const float* A2b = A2 ? A2 + (size_t)b * sA2 * NP : A1;
    int tid = threadIdx.x;
    int tx = tid & 15, ty = tid >> 4;

    float acc[8][8];
#pragma unroll
    for (int i = 0; i < 8; i++)
#pragma unroll
        for (int j = 0; j < 8; j++) acc[i][j] = 0.f;

    for (int k0 = 0; k0 < K; k0 += BKK) {
#pragma unroll
        for (int i = 0; i < 4; i++) {
            int e = tid + i * 256;
            int r = e >> 3, kk = e & 7;
            int o = o0 + r;
            As[kk][r] = (o < Cout) ? W[(size_t)o * K + k0 + kk] : 0.f;
        }
#pragma unroll
        for (int i = 0; i < 4; i++) {
            int e = tid + i * 256;
            int kk = e >> 7, pp = e & 127;
            int kg = k0 + kk;
            const float* src = (kg < K1) ? (A1b + (size_t)kg * NP)
                                         : (A2b + (size_t)(kg - K1) * NP);
            Bs[kk][pp] = src[p0 + pp];
        }
        __syncthreads();
#pragma unroll
        for (int kk = 0; kk < BKK; kk++) {
            float a[8], bb[8];
#pragma unroll
            for (int i = 0; i < 8; i++) a[i] = As[kk][ty * 8 + i];
#pragma unroll
            for (int j = 0; j < 8; j++) bb[j] = Bs[kk][tx * 8 + j];
#pragma unroll
            for (int i = 0; i < 8; i++)
#pragma unroll
                for (int j = 0; j < 8; j++)
                    acc[i][j] = fmaf(a[i], bb[j], acc[i][j]);
        }
        __syncthreads();
    }

    float* Yb = Y + (size_t)b * sY * NP;
    const float* E1b = E1 ? E1 + (size_t)b * sE1 * NP : nullptr;
    const float* E2b = E2 ? E2 + (size_t)b * sE2 * NP : nullptr;
#pragma unroll
    for (int i = 0; i < 8; i++) {
        int o = o0 + ty * 8 + i;
        if (o >= Cout) break;
#pragma unroll
        for (int j = 0; j < 8; j++) {
            int p = p0 + tx * 8 + j;
            float g = acc[i][j];
            float outv;
            if (mode == 0) {
                outv = g;
            } else if (mode == 1) {
                outv = g + E1b[(size_t)o * NP + p];
            } else if (mode == 2) {
                float base = (o < Chalf) ? E1b[(size_t)o * NP + p]
                                         : E2b[(size_t)(o - Chalf) * NP + p];
                outv = g * base + base;
            } else {
                float r  = g + E1b[(size_t)o * NP + p];
                float xg = E2b[(size_t)o * NP + p];
                float gel = 0.5f * xg * (1.f + erff(xg * 0.70710678118654752f));
                outv = gel * r;
            }
            Yb[(size_t)o * NP + p] = outv;
        }
    }
}

// ---------------- depthwise 3x3, SAME zero pad ----------------
__global__ void dw_kernel(const float* __restrict__ in, const float* __restrict__ w,
                          float* __restrict__ out, int C)
{
    int b = blockIdx.z, c = blockIdx.y;
    int p = blockIdx.x * 256 + threadIdx.x;
    int y = p >> 7, x = p & 127;
    const float* ib = in + ((size_t)b * C + c) * NP;
    const float* wc = w + c * 9;
    float acc = 0.f;
#pragma unroll
    for (int dy = -1; dy <= 1; dy++) {
        int yy = y + dy;
        if (yy < 0 || yy > 127) continue;
#pragma unroll
        for (int dx = -1; dx <= 1; dx++) {
            int xx = x + dx;
            if (xx < 0 || xx > 127) continue;
            acc = fmaf(ib[yy * 128 + xx], wc[(dy + 1) * 3 + (dx + 1)], acc);
        }
    }
    out[((size_t)b * C + c) * NP + p] = acc;
}

// ---------------- row L2 norms of q,k (channels 0..383 of QKV) ----------------
__global__ void norm_kernel(const float* __restrict__ qkv, float* __restrict__ nrm)
{
    int r = blockIdx.x;              // 0..767
    int b = r / 384, c = r % 384;
    const float* src = qkv + ((size_t)b * 576 + c) * NP;
    float s = 0.f;
    for (int i = threadIdx.x; i < NP; i += 256) {
        float v = src[i];
        s += v * v;
    }
    __shared__ float red[256];
    red[threadIdx.x] = s;
    __syncthreads();
    for (int st = 128; st > 0; st >>= 1) {
        if (threadIdx.x < st) red[threadIdx.x] += red[threadIdx.x + st];
        __syncthreads();
    }
    if (threadIdx.x == 0) nrm[r] = fmaxf(sqrtf(red[0]), 1e-12f);
}

// ---------------- attention scores: S_part[ks][bh][c][d] = sum_p q[c,p]k[d,p] ----
__global__ void scores_kernel(const float* __restrict__ qkv, float* __restrict__ S)
{
    int bh = blockIdx.x;             // 0..11
    int ks = blockIdx.y;             // 0..KSPLIT-1
    int b = bh / 6, h = bh % 6;
    const float* qb = qkv + ((size_t)b * 576 + h * 32) * NP;
    const float* kb = qkv + ((size_t)b * 576 + 192 + h * 32) * NP;
    __shared__ float qs[32][65], ksm[32][65];
    int tid = threadIdx.x;
    int c = tid >> 3, d0 = (tid & 7) * 4;
    float acc[4] = {0.f, 0.f, 0.f, 0.f};
    int kbase = ks * (NP / KSPLIT);
    for (int t = 0; t < (NP / KSPLIT) / 64; t++) {
        int k0 = kbase + t * 64;
#pragma unroll
        for (int i = 0; i < 8; i++) {
            int e = tid + i * 256;
            int row = e >> 6, col = e & 63;
            qs[row][col]  = qb[(size_t)row * NP + k0 + col];
            ksm[row][col] = kb[(size_t)row * NP + k0 + col];
        }
        __syncthreads();
#pragma unroll
        for (int kk = 0; kk < 64; kk++) {
            float qv = qs[c][kk];
#pragma unroll
            for (int j = 0; j < 4; j++)
                acc[j] = fmaf(qv, ksm[d0 + j][kk], acc[j]);
        }
        __syncthreads();
    }
    float* Sp = S + (size_t)ks * 12288 + bh * 1024 + c * 32 + d0;
#pragma unroll
    for (int j = 0; j < 4; j++) Sp[j] = acc[j];
}

// ---------------- softmax over d, with normalization + temperature ----------------
__global__ void softmax_kernel(float* __restrict__ S, const float* __restrict__ nrm,
                               const float* __restrict__ temp)
{
    int bh = blockIdx.y;             // 0..11
    int c  = blockIdx.x;             // 0..31
    int b = bh / 6, h = bh % 6;
    int d = threadIdx.x;             // 0..31
    float acc = 0.f;
    size_t idx = (size_t)bh * 1024 + c * 32 + d;
    for (int j = 0; j < KSPLIT; j++) acc += S[(size_t)j * 12288 + idx];
    float nq = nrm[b * 384 + h * 32 + c];
    float nk = nrm[b * 384 + 192 + h * 32 + d];
    float v = acc / (nq * nk) * temp[h];
    float m = v;
    for (int o = 16; o; o >>= 1) m = fmaxf(m, __shfl_xor_sync(0xffffffffu, m, o));
    float e = expf(v - m);
    float s = e;
    for (int o = 16; o; o >>= 1) s += __shfl_xor_sync(0xffffffffu, s, o);
    S[idx] = e / s;                  // store final attn into partial-0 slot
}

// ---------------- out = attn @ v ----------------
__global__ void av_kernel(const float* __restrict__ S, const float* __restrict__ qkv,
                          float* __restrict__ out)
{
    int b = blockIdx.z, h = blockIdx.y;
    int p = blockIdx.x * 128 + threadIdx.x;
    __shared__ float A[32][32];
    int bh = b * 6 + h;
    for (int i = threadIdx.x; i < 1024; i += 128)
        A[i >> 5][i & 31] = S[(size_t)bh * 1024 + i];
    __syncthreads();
    const float* vb = qkv + ((size_t)b * 576 + 384 + h * 32) * NP + p;
    float vr[32];
#pragma unroll
    for (int d = 0; d < 32; d++) vr[d] = vb[(size_t)d * NP];
    float* ob = out + ((size_t)b * 192 + h * 32) * NP + p;
#pragma unroll
    for (int c = 0; c < 32; c++) {
        float acc = 0.f;
#pragma unroll
        for (int d = 0; d < 32; d++) acc = fmaf(A[c][d], vr[d], acc);
        ob[(size_t)c * NP] = acc;
    }
}

// ---------------- host orchestration ----------------
static inline void launch_gemm(const float* W, int K,
                               const float* A1, int K1, int sA1,
                               const float* A2, int sA2,
                               int Cout,
                               const float* E1, int sE1,
                               const float* E2, int sE2,
                               float* Y, int sY, int mode, int Chalf)
{
    dim3 grid(NP / BN, (Cout + BM - 1) / BM, NB);
    gemm_kernel<<<grid, 256>>>(W, K, A1, K1, sA1, A2, sA2, Cout,
                               E1, sE1, E2, sE2, Y, sY, mode, Chalf);
}

extern "C" void kernel_launch(void* const* d_in, const int* in_sizes, int n_in,
                              void* d_out, int out_size)
{
    const float* x       = (const float*)d_in[0];
    const float* feature = (const float*)d_in[1];
    const float* nf_w = (const float*)d_in[2];
    const float* nf_b = (const float*)d_in[3];
    const float* n1_w = (const float*)d_in[4];
    const float* n1_b = (const float*)d_in[5];
    const float* n2_w = (const float*)d_in[6];
    const float* n2_b = (const float*)d_in[7];
    const float* a_cc_w   = (const float*)d_in[8];    // [384,384]
    const float* a_fus_w  = (const float*)d_in[9];    // [192,384]
    const float* a_msk_w  = (const float*)d_in[10];   // [192,192]
    const float* a_qkv_w  = (const float*)d_in[11];   // [576,192]
    const float* a_qkvdw  = (const float*)d_in[12];   // [576,1,3,3]
    const float* a_temp   = (const float*)d_in[13];   // [6]
    const float* a_proj_w = (const float*)d_in[14];   // [192,192]
    const float* f_pm_w   = (const float*)d_in[15];   // [576,192]
    const float* f_pi_w   = (const float*)d_in[16];   // [1152,192]
    const float* f_dw_w   = (const float*)d_in[17];   // [1152,1,3,3]
    const float* f_cc_w   = (const float*)d_in[18];   // [1152,1152]
    const float* f_fus_w  = (const float*)d_in[19];   // [576,1152]
    const float* f_msk_w  = (const float*)d_in[20];   // [576,576]
    const float* f_po_w   = (const float*)d_in[21];   // [192,576]
    float* out = (float*)d_out;

    float* base = nullptr;
    cudaGetSymbolAddress((void**)&base, g_scratch);
    float* F     = base + OFF_F;
    float* X1    = base + OFF_X1;
    float* MT    = base + OFF_MT;
    float* OUTD  = base + OFF_OUTD;
    float* ATTIN = base + OFF_ATTIN;
    float* QKV0  = base + OFF_QKV0;
    float* QKV   = base + OFF_QKV;
    float* OUTA  = base + OFF_OUTA;
    float* XMID  = base + OFF_XMID;
    float* X2L   = base + OFF_X2L;
    float* FM    = base + OFF_FM;
    float* XIN   = base + OFF_XIN;
    float* DW    = base + OFF_DW;
    float* MT2   = base + OFF_MT2;
    float* OUT2  = base + OFF_OUT2;
    float* GX    = base + OFF_GX;
    float* NRM   = base + OFF_NRM;
    float* S     = base + OFF_S;

    dim3 lng(NP / 256, NB);

    // feat = LN(feature); x1 = LN(x)
    ln_kernel<<<lng, 256>>>(feature, nf_w, nf_b, F, 192);
    ln_kernel<<<lng, 256>>>(x, n1_w, n1_b, X1, 192);

    // --- attention DDF ---
    launch_gemm(a_msk_w, 192, F, 192, 192, nullptr, 0, 192,
                nullptr, 0, nullptr, 0, MT, 192, 0, 0);
    launch_gemm(a_cc_w, 384, X1, 192, 192, MT, 192, 384,
                X1, 192, MT, 192, OUTD, 384, 2, 192);
    launch_gemm(a_fus_w, 384, OUTD, 384, 384, nullptr, 0, 192,
                X1, 192, nullptr, 0, ATTIN, 192, 1, 0);

    // qkv + depthwise
    launch_gemm(a_qkv_w, 192, ATTIN, 192, 192, nullptr, 0, 576,
                nullptr, 0, nullptr, 0, QKV0, 576, 0, 0);
    dw_kernel<<<dim3(NP / 256, 576, NB), 256>>>(QKV0, a_qkvdw, QKV, 576);

    // channel attention
    norm_kernel<<<768, 256>>>(QKV, NRM);
    scores_kernel<<<dim3(12, KSPLIT), 256>>>(QKV, S);
    softmax_kernel<<<dim3(32, 12), 32>>>(S, NRM, a_temp);
    av_kernel<<<dim3(NP / 128, 6, NB), 128>>>(S, QKV, OUTA);

    // proj + residual with original x
    launch_gemm(a_proj_w, 192, OUTA, 192, 192, nullptr, 0, 192,
                x, 192, nullptr, 0, XMID, 192, 1, 0);

    // --- FFN ---
    ln_kernel<<<lng, 256>>>(XMID, n2_w, n2_b, X2L, 192);
    launch_gemm(f_pm_w, 192, F, 192, 192, nullptr, 0, 576,
                nullptr, 0, nullptr, 0, FM, 576, 0, 0);
    launch_gemm(f_pi_w, 192, X2L, 192, 192, nullptr, 0, 1152,
                nullptr, 0, nullptr, 0, XIN, 1152, 0, 0);
    dw_kernel<<<dim3(NP / 256, 1152, NB), 256>>>(XIN, f_dw_w, DW, 1152);

    const float* X2H = DW + (size_t)576 * NP;   // second half of DW, batch-stride 1152
    launch_gemm(f_msk_w, 576, FM, 576, 576, nullptr, 0, 576,
                nullptr, 0, nullptr, 0, MT2, 576, 0, 0);
    launch_gemm(f_cc_w, 1152, X2H, 576, 1152, MT2, 576, 1152,
                X2H, 1152, MT2, 576, OUT2, 1152, 2, 576);
    // fused2 = fusion@OUT2 + X2H ; GX = gelu(X1H) * fused2
    launch_gemm(f_fus_w, 1152, OUT2, 1152, 1152, nullptr, 0, 576,
                X2H, 1152, DW, 1152, GX, 576, 3, 0);
    // out = XMID + projout@GX
    launch_gemm(f_po_w, 576, GX, 576, 576, nullptr, 0, 192,
                XMID, 192, nullptr, 0, out, 192, 1, 0);
}

// round 4
// speedup vs baseline: 1.9633x; 1.9633x over previous
#include <cuda_runtime.h>
#include <cuda_bf16.h>
#include <math.h>
#include <stdint.h>

// ---------------- problem constants ----------------
#define NP 16384            // H*W per batch
#define NB 2                // batch
#define PL (NB * NP)        // floats per channel across batch

#define OFF_F      ((size_t)0)
#define OFF_X1     (OFF_F     + (size_t)192  * PL)
#define OFF_MT     (OFF_X1    + (size_t)192  * PL)
#define OFF_OUTD   (OFF_MT    + (size_t)192  * PL)
#define OFF_ATTIN  (OFF_OUTD  + (size_t)384  * PL)
#define OFF_QKV0   (OFF_ATTIN + (size_t)192  * PL)
#define OFF_QKV    (OFF_QKV0  + (size_t)576  * PL)
#define OFF_OUTA   (OFF_QKV   + (size_t)576  * PL)
#define OFF_XMID   (OFF_OUTA  + (size_t)192  * PL)
#define OFF_X2L    (OFF_XMID  + (size_t)192  * PL)
#define OFF_FM     (OFF_X2L   + (size_t)192  * PL)
#define OFF_XIN    (OFF_FM    + (size_t)576  * PL)
#define OFF_DW     (OFF_XIN   + (size_t)1152 * PL)
#define OFF_MT2    (OFF_DW    + (size_t)1152 * PL)
#define OFF_OUT2   (OFF_MT2   + (size_t)576  * PL)
#define OFF_GX     (OFF_OUT2  + (size_t)1152 * PL)
#define OFF_NRM    (OFF_GX    + (size_t)576  * PL)
#define OFF_S      (OFF_NRM   + (size_t)1024)
#define KSPLIT 16
#define SCRATCH_FLOATS (OFF_S + (size_t)KSPLIT * 12288)

__device__ float g_scratch[SCRATCH_FLOATS];

// ================= helpers =================
__device__ __forceinline__ uint32_t smem_u32(const void* p) {
    uint32_t a;
    asm("{ .reg .u64 t; cvta.to.shared.u64 t, %1; cvt.u32.u64 %0, t; }"
        : "=r"(a) : "l"(p));
    return a;
}
__device__ __forceinline__ uint32_t lds32(uint32_t a) {
    uint32_t v;
    asm volatile("ld.shared.b32 %0, [%1];" : "=r"(v) : "r"(a));
    return v;
}
__device__ __forceinline__ void sts128(uint32_t a, uint32_t x, uint32_t y,
                                       uint32_t z, uint32_t w) {
    asm volatile("st.shared.v4.b32 [%0], {%1,%2,%3,%4};"
                 :: "r"(a), "r"(x), "r"(y), "r"(z), "r"(w));
}
__device__ __forceinline__ void mma16816(float c[4], const uint32_t a[4],
                                         const uint32_t b[2]) {
    asm volatile(
        "mma.sync.aligned.m16n8k16.row.col.f32.bf16.bf16.f32 "
        "{%0,%1,%2,%3},{%4,%5,%6,%7},{%8,%9},{%0,%1,%2,%3};"
        : "+f"(c[0]), "+f"(c[1]), "+f"(c[2]), "+f"(c[3])
        : "r"(a[0]), "r"(a[1]), "r"(a[2]), "r"(a[3]), "r"(b[0]), "r"(b[1]));
}
// fp32 pair -> bf16 hi pair + bf16 lo pair (lo element in low 16 bits)
__device__ __forceinline__ void hilo2(float v0, float v1, uint32_t& hp, uint32_t& lp) {
    __nv_bfloat16 h0 = __float2bfloat16_rn(v0);
    __nv_bfloat16 h1 = __float2bfloat16_rn(v1);
    float r0 = v0 - __bfloat162float(h0);
    float r1 = v1 - __bfloat162float(h1);
    __nv_bfloat16 l0 = __float2bfloat16_rn(r0);
    __nv_bfloat16 l1 = __float2bfloat16_rn(r1);
    hp = ((uint32_t)__bfloat16_as_ushort(h1) << 16) | __bfloat16_as_ushort(h0);
    lp = ((uint32_t)__bfloat16_as_ushort(l1) << 16) | __bfloat16_as_ushort(l0);
}

// ================= HMMA GEMM =================
// Y[o,p] = sum_k W[o,k]*Acat[k,p] (+epilogue). CTA tile 128(M) x 128(N), BK=32.
// bf16 hi/lo split: D += Ah*Bh + Al*Bh + Ah*Bl  (err ~2^-18).
// SMEM per buffer: Ah|Al|Bh|Bl planes, each 128 rows x 40 bf16 (32+8 pad) = 10240B.
#define PLANE 10240
#define BUFSZ (4 * PLANE)          // 40960
#define GSMEM (2 * BUFSZ)          // 81920 dynamic

__global__ void __launch_bounds__(256, 1)
hmma_gemm(const float* __restrict__ W, int K,
          const float* __restrict__ A1, int K1, int sA1,
          const float* __restrict__ A2, int sA2,
          int Cout,
          const float* __restrict__ E1, int sE1,
          const float* __restrict__ E2, int sE2,
          float* __restrict__ Y, int sY,
          int mode, int Chalf)
{
    extern __shared__ char smem[];
    const uint32_t sb = smem_u32(smem);
    const int tid = threadIdx.x, wid = tid >> 5, lane = tid & 31;
    const int g = lane >> 2, tig = lane & 3;
    const int wm = wid & 3, wn = wid >> 2;       // 4 M-warps x 2 N-warps
    const int b  = blockIdx.z;
    const int p0 = blockIdx.x * 128;
    const int o0 = blockIdx.y * 128;

    const float* A1b = A1 + (size_t)b * sA1 * NP;
    const float* A2b = A2 ? A2 + (size_t)b * sA2 * NP : A1;

    // loader roles
    const int rowA  = tid >> 1,  halfA = tid & 1;    // A: row (M), 16-k half
    const int pB    = tid & 127, halfB = tid >> 7;   // B: pixel, 16-k half
    const int orow  = o0 + rowA;
    const bool wvalid = (orow < Cout);
    const float* wrow = W + (size_t)orow * K;

    float vA[16], vB[16];
    auto ldg = [&](int kc) {
        const float* srcA = wrow + kc + halfA * 16;
#pragma unroll
        for (int q = 0; q < 4; q++) {
            float4 f = wvalid ? *(const float4*)(srcA + q * 4)
                              : make_float4(0.f, 0.f, 0.f, 0.f);
            vA[q * 4 + 0] = f.x; vA[q * 4 + 1] = f.y;
            vA[q * 4 + 2] = f.z; vA[q * 4 + 3] = f.w;
        }
#pragma unroll
        for (int kk = 0; kk < 16; kk++) {
            int kg = kc + halfB * 16 + kk;
            const float* s = (kg < K1) ? (A1b + (size_t)kg * NP)
                                       : (A2b + (size_t)(kg - K1) * NP);
            vB[kk] = s[p0 + pB];
        }
    };
    auto sts = [&](int buf) {
        uint32_t base = sb + buf * BUFSZ;
        uint32_t h[8], l[8];
#pragma unroll
        for (int j = 0; j < 8; j++) hilo2(vA[2 * j], vA[2 * j + 1], h[j], l[j]);
        uint32_t offA = base + rowA * 80 + halfA * 32;
        sts128(offA,              h[0], h[1], h[2], h[3]);
        sts128(offA + 16,         h[4], h[5], h[6], h[7]);
        sts128(offA + PLANE,      l[0], l[1], l[2], l[3]);
        sts128(offA + PLANE + 16, l[4], l[5], l[6], l[7]);
#pragma unroll
        for (int j = 0; j < 8; j++) hilo2(vB[2 * j], vB[2 * j + 1], h[j], l[j]);
        uint32_t offB = base + 2 * PLANE + pB * 80 + halfB * 32;
        sts128(offB,              h[0], h[1], h[2], h[3]);
        sts128(offB + 16,         h[4], h[5], h[6], h[7]);
        sts128(offB + PLANE,      l[0], l[1], l[2], l[3]);
        sts128(offB + PLANE + 16, l[4], l[5], l[6], l[7]);
    };

    float acc[2][8][4];
#pragma unroll
    for (int i = 0; i < 2; i++)
#pragma unroll
        for (int j = 0; j < 8; j++)
#pragma unroll
            for (int q = 0; q < 4; q++) acc[i][j][q] = 0.f;

    const int nch = K >> 5;
    ldg(0);
    sts(0);
    __syncthreads();

    for (int c = 0; c < nch; c++) {
        const bool more = (c + 1 < nch);
        if (more) ldg((c + 1) * 32);

        uint32_t base = sb + (c & 1) * BUFSZ;
        uint32_t ahB = base, alB = base + PLANE;
        uint32_t bhB = base + 2 * PLANE, blB = base + 3 * PLANE;
#pragma unroll
        for (int s = 0; s < 2; s++) {
            uint32_t ah[2][4], al[2][4], bh[8][2], bl[8][2];
#pragma unroll
            for (int i = 0; i < 2; i++) {
                uint32_t off = (uint32_t)(wm * 32 + i * 16 + g) * 80 + s * 32 + tig * 4;
                ah[i][0] = lds32(ahB + off);       ah[i][1] = lds32(ahB + off + 640);
                ah[i][2] = lds32(ahB + off + 16);  ah[i][3] = lds32(ahB + off + 656);
                al[i][0] = lds32(alB + off);       al[i][1] = lds32(alB + off + 640);
                al[i][2] = lds32(alB + off + 16);  al[i][3] = lds32(alB + off + 656);
            }
#pragma unroll
            for (int j = 0; j < 8; j++) {
                uint32_t off = (uint32_t)(wn * 64 + j * 8 + g) * 80 + s * 32 + tig * 4;
                bh[j][0] = lds32(bhB + off); bh[j][1] = lds32(bhB + off + 16);
                bl[j][0] = lds32(blB + off); bl[j][1] = lds32(blB + off + 16);
            }
#pragma unroll
            for (int i = 0; i < 2; i++)
#pragma unroll
                for (int j = 0; j < 8; j++) {
                    mma16816(acc[i][j], ah[i], bh[j]);
                    mma16816(acc[i][j], al[i], bh[j]);
                    mma16816(acc[i][j], ah[i], bl[j]);
                }
        }
        if (more) sts((c + 1) & 1);
        __syncthreads();
    }

    // ---- epilogue ----
    float* Yb = Y + (size_t)b * sY * NP;
    const float* E1b = E1 ? E1 + (size_t)b * sE1 * NP : nullptr;
    const float* E2b = E2 ? E2 + (size_t)b * sE2 * NP : nullptr;
    const int obase = o0 + wm * 32;
    const int pbase = p0 + wn * 64;

    auto emit = [&](int o, int p, float d0, float d1) {
        if (o >= Cout) return;
        float y0, y1;
        if (mode == 0) {
            y0 = d0; y1 = d1;
        } else if (mode == 1) {
            const float* e = E1b + (size_t)o * NP + p;
            y0 = d0 + e[0]; y1 = d1 + e[1];
        } else if (mode == 2) {
            const float* br = (o < Chalf) ? (E1b + (size_t)o * NP + p)
                                          : (E2b + (size_t)(o - Chalf) * NP + p);
            y0 = d0 * br[0] + br[0]; y1 = d1 * br[1] + br[1];
        } else {
            const float* e1 = E1b + (size_t)o * NP + p;
            const float* e2 = E2b + (size_t)o * NP + p;
            float r0 = d0 + e1[0], r1 = d1 + e1[1];
            float xg0 = e2[0], xg1 = e2[1];
            float g0 = 0.5f * xg0 * (1.f + erff(xg0 * 0.70710678118654752f));
            float g1 = 0.5f * xg1 * (1.f + erff(xg1 * 0.70710678118654752f));
            y0 = g0 * r0; y1 = g1 * r1;
        }
        *(float2*)(Yb + (size_t)o * NP + p) = make_float2(y0, y1);
    };

#pragma unroll
    for (int i = 0; i < 2; i++) {
#pragma unroll
        for (int j = 0; j < 8; j++) {
            int oA = obase + i * 16 + g;
            int p  = pbase + j * 8 + tig * 2;
            emit(oA,     p, acc[i][j][0], acc[i][j][1]);
            emit(oA + 8, p, acc[i][j][2], acc[i][j][3]);
        }
    }
}

// ---------------- LayerNorm over channel dim ----------------
__global__ void ln_kernel(const float* __restrict__ in, const float* __restrict__ g,
                          const float* __restrict__ be, float* __restrict__ out, int C)
{
    int b = blockIdx.y;
    int p = blockIdx.x * 256 + threadIdx.x;
    const float* ib = in + (size_t)b * C * NP + p;
    float s = 0.f, ss = 0.f;
    for (int c = 0; c < C; c++) {
        float v = ib[(size_t)c * NP];
        s += v; ss += v * v;
    }
    float mu = s / C;
    float var = ss / C - mu * mu;
    float rstd = rsqrtf(var + 1e-5f);
    float* ob = out + (size_t)b * C * NP + p;
    for (int c = 0; c < C; c++) {
        float v = ib[(size_t)c * NP];
        ob[(size_t)c * NP] = (v - mu) * rstd * g[c] + be[c];
    }
}

// ---------------- depthwise 3x3, SAME zero pad ----------------
__global__ void dw_kernel(const float* __restrict__ in, const float* __restrict__ w,
                          float* __restrict__ out, int C)
{
    int b = blockIdx.z, c = blockIdx.y;
    int p = blockIdx.x * 256 + threadIdx.x;
    int y = p >> 7, x = p & 127;
    const float* ib = in + ((size_t)b * C + c) * NP;
    const float* wc = w + c * 9;
    float acc = 0.f;
#pragma unroll
    for (int dy = -1; dy <= 1; dy++) {
        int yy = y + dy;
        if (yy < 0 || yy > 127) continue;
#pragma unroll
        for (int dx = -1; dx <= 1; dx++) {
            int xx = x + dx;
            if (xx < 0 || xx > 127) continue;
            acc = fmaf(ib[yy * 128 + xx], wc[(dy + 1) * 3 + (dx + 1)], acc);
        }
    }
    out[((size_t)b * C + c) * NP + p] = acc;
}

// ---------------- row L2 norms of q,k ----------------
__global__ void norm_kernel(const float* __restrict__ qkv, float* __restrict__ nrm)
{
    int r = blockIdx.x;              // 0..767
    int b = r / 384, c = r % 384;
    const float* src = qkv + ((size_t)b * 576 + c) * NP;
    float s = 0.f;
    for (int i = threadIdx.x; i < NP; i += 256) {
        float v = src[i];
        s += v * v;
    }
    __shared__ float red[256];
    red[threadIdx.x] = s;
    __syncthreads();
    for (int st = 128; st > 0; st >>= 1) {
        if (threadIdx.x < st) red[threadIdx.x] += red[threadIdx.x + st];
        __syncthreads();
    }
    if (threadIdx.x == 0) nrm[r] = fmaxf(sqrtf(red[0]), 1e-12f);
}

// ---------------- attention scores ----------------
__global__ void scores_kernel(const float* __restrict__ qkv, float* __restrict__ S)
{
    int bh = blockIdx.x;
    int ks = blockIdx.y;
    int b = bh / 6, h = bh % 6;
    const float* qb = qkv + ((size_t)b * 576 + h * 32) * NP;
    const float* kb = qkv + ((size_t)b * 576 + 192 + h * 32) * NP;
    __shared__ float qs[32][65], ksm[32][65];
    int tid = threadIdx.x;
    int c = tid >> 3, d0 = (tid & 7) * 4;
    float acc[4] = {0.f, 0.f, 0.f, 0.f};
    int kbase = ks * (NP / KSPLIT);
    for (int t = 0; t < (NP / KSPLIT) / 64; t++) {
        int k0 = kbase + t * 64;
#pragma unroll
        for (int i = 0; i < 8; i++) {
            int e = tid + i * 256;
            int row = e >> 6, col = e & 63;
            qs[row][col]  = qb[(size_t)row * NP + k0 + col];
            ksm[row][col] = kb[(size_t)row * NP + k0 + col];
        }
        __syncthreads();
#pragma unroll
        for (int kk = 0; kk < 64; kk++) {
            float qv = qs[c][kk];
#pragma unroll
            for (int j = 0; j < 4; j++)
                acc[j] = fmaf(qv, ksm[d0 + j][kk], acc[j]);
        }
        __syncthreads();
    }
    float* Sp = S + (size_t)ks * 12288 + bh * 1024 + c * 32 + d0;
#pragma unroll
    for (int j = 0; j < 4; j++) Sp[j] = acc[j];
}

// ---------------- softmax with norm + temperature ----------------
__global__ void softmax_kernel(float* __restrict__ S, const float* __restrict__ nrm,
                               const float* __restrict__ temp)
{
    int bh = blockIdx.y;
    int c  = blockIdx.x;
    int b = bh / 6, h = bh % 6;
    int d = threadIdx.x;
    float acc = 0.f;
    size_t idx = (size_t)bh * 1024 + c * 32 + d;
    for (int j = 0; j < KSPLIT; j++) acc += S[(size_t)j * 12288 + idx];
    float nq = nrm[b * 384 + h * 32 + c];
    float nk = nrm[b * 384 + 192 + h * 32 + d];
    float v = acc / (nq * nk) * temp[h];
    float m = v;
    for (int o = 16; o; o >>= 1) m = fmaxf(m, __shfl_xor_sync(0xffffffffu, m, o));
    float e = expf(v - m);
    float s = e;
    for (int o = 16; o; o >>= 1) s += __shfl_xor_sync(0xffffffffu, s, o);
    S[idx] = e / s;
}

// ---------------- out = attn @ v ----------------
__global__ void av_kernel(const float* __restrict__ S, const float* __restrict__ qkv,
                          float* __restrict__ out)
{
    int b = blockIdx.z, h = blockIdx.y;
    int p = blockIdx.x * 128 + threadIdx.x;
    __shared__ float A[32][32];
    int bh = b * 6 + h;
    for (int i = threadIdx.x; i < 1024; i += 128)
        A[i >> 5][i & 31] = S[(size_t)bh * 1024 + i];
    __syncthreads();
    const float* vb = qkv + ((size_t)b * 576 + 384 + h * 32) * NP + p;
    float vr[32];
#pragma unroll
    for (int d = 0; d < 32; d++) vr[d] = vb[(size_t)d * NP];
    float* ob = out + ((size_t)b * 192 + h * 32) * NP + p;
#pragma unroll
    for (int c = 0; c < 32; c++) {
        float acc = 0.f;
#pragma unroll
        for (int d = 0; d < 32; d++) acc = fmaf(A[c][d], vr[d], acc);
        ob[(size_t)c * NP] = acc;
    }
}

// ---------------- host orchestration ----------------
static inline void launch_gemm(const float* W, int K,
                               const float* A1, int K1, int sA1,
                               const float* A2, int sA2,
                               int Cout,
                               const float* E1, int sE1,
                               const float* E2, int sE2,
                               float* Y, int sY, int mode, int Chalf)
{
    dim3 grid(NP / 128, (Cout + 127) / 128, NB);
    hmma_gemm<<<grid, 256, GSMEM>>>(W, K, A1, K1, sA1, A2, sA2, Cout,
                                    E1, sE1, E2, sE2, Y, sY, mode, Chalf);
}

extern "C" void kernel_launch(void* const* d_in, const int* in_sizes, int n_in,
                              void* d_out, int out_size)
{
    const float* x       = (const float*)d_in[0];
    const float* feature = (const float*)d_in[1];
    const float* nf_w = (const float*)d_in[2];
    const float* nf_b = (const float*)d_in[3];
    const float* n1_w = (const float*)d_in[4];
    const float* n1_b = (const float*)d_in[5];
    const float* n2_w = (const float*)d_in[6];
    const float* n2_b = (const float*)d_in[7];
    const float* a_cc_w   = (const float*)d_in[8];
    const float* a_fus_w  = (const float*)d_in[9];
    const float* a_msk_w  = (const float*)d_in[10];
    const float* a_qkv_w  = (const float*)d_in[11];
    const float* a_qkvdw  = (const float*)d_in[12];
    const float* a_temp   = (const float*)d_in[13];
    const float* a_proj_w = (const float*)d_in[14];
    const float* f_pm_w   = (const float*)d_in[15];
    const float* f_pi_w   = (const float*)d_in[16];
    const float* f_dw_w   = (const float*)d_in[17];
    const float* f_cc_w   = (const float*)d_in[18];
    const float* f_fus_w  = (const float*)d_in[19];
    const float* f_msk_w  = (const float*)d_in[20];
    const float* f_po_w   = (const float*)d_in[21];
    float* out = (float*)d_out;

    cudaFuncSetAttribute(hmma_gemm, cudaFuncAttributeMaxDynamicSharedMemorySize, GSMEM);

    float* base = nullptr;
    cudaGetSymbolAddress((void**)&base, g_scratch);
    float* F     = base + OFF_F;
    float* X1    = base + OFF_X1;
    float* MT    = base + OFF_MT;
    float* OUTD  = base + OFF_OUTD;
    float* ATTIN = base + OFF_ATTIN;
    float* QKV0  = base + OFF_QKV0;
    float* QKV   = base + OFF_QKV;
    float* OUTA  = base + OFF_OUTA;
    float* XMID  = base + OFF_XMID;
    float* X2L   = base + OFF_X2L;
    float* FM    = base + OFF_FM;
    float* XIN   = base + OFF_XIN;
    float* DW    = base + OFF_DW;
    float* MT2   = base + OFF_MT2;
    float* OUT2  = base + OFF_OUT2;
    float* GX    = base + OFF_GX;
    float* NRM   = base + OFF_NRM;
    float* S     = base + OFF_S;

    dim3 lng(NP / 256, NB);

    ln_kernel<<<lng, 256>>>(feature, nf_w, nf_b, F, 192);
    ln_kernel<<<lng, 256>>>(x, n1_w, n1_b, X1, 192);

    // --- attention DDF ---
    launch_gemm(a_msk_w, 192, F, 192, 192, nullptr, 0, 192,
                nullptr, 0, nullptr, 0, MT, 192, 0, 0);
    launch_gemm(a_cc_w, 384, X1, 192, 192, MT, 192, 384,
                X1, 192, MT, 192, OUTD, 384, 2, 192);
    launch_gemm(a_fus_w, 384, OUTD, 384, 384, nullptr, 0, 192,
                X1, 192, nullptr, 0, ATTIN, 192, 1, 0);

    // qkv + depthwise
    launch_gemm(a_qkv_w, 192, ATTIN, 192, 192, nullptr, 0, 576,
                nullptr, 0, nullptr, 0, QKV0, 576, 0, 0);
    dw_kernel<<<dim3(NP / 256, 576, NB), 256>>>(QKV0, a_qkvdw, QKV, 576);

    // channel attention
    norm_kernel<<<768, 256>>>(QKV, NRM);
    scores_kernel<<<dim3(12, KSPLIT), 256>>>(QKV, S);
    softmax_kernel<<<dim3(32, 12), 32>>>(S, NRM, a_temp);
    av_kernel<<<dim3(NP / 128, 6, NB), 128>>>(S, QKV, OUTA);

    // proj + residual with original x
    launch_gemm(a_proj_w, 192, OUTA, 192, 192, nullptr, 0, 192,
                x, 192, nullptr, 0, XMID, 192, 1, 0);

    // --- FFN ---
    ln_kernel<<<lng, 256>>>(XMID, n2_w, n2_b, X2L, 192);
    launch_gemm(f_pm_w, 192, F, 192, 192, nullptr, 0, 576,
                nullptr, 0, nullptr, 0, FM, 576, 0, 0);
    launch_gemm(f_pi_w, 192, X2L, 192, 192, nullptr, 0, 1152,
                nullptr, 0, nullptr, 0, XIN, 1152, 0, 0);
    dw_kernel<<<dim3(NP / 256, 1152, NB), 256>>>(XIN, f_dw_w, DW, 1152);

    const float* X2H = DW + (size_t)576 * NP;
    launch_gemm(f_msk_w, 576, FM, 576, 576, nullptr, 0, 576,
                nullptr, 0, nullptr, 0, MT2, 576, 0, 0);
    launch_gemm(f_cc_w, 1152, X2H, 576, 1152, MT2, 576, 1152,
                X2H, 1152, MT2, 576, OUT2, 1152, 2, 576);
    launch_gemm(f_fus_w, 1152, OUT2, 1152, 1152, nullptr, 0, 576,
                X2H, 1152, DW, 1152, GX, 576, 3, 0);
    launch_gemm(f_po_w, 576, GX, 576, 576, nullptr, 0, 192,
                XMID, 192, nullptr, 0, out, 192, 1, 0);
}

// round 5
// speedup vs baseline: 2.3306x; 1.1871x over previous
#include <cuda_runtime.h>
#include <cuda_bf16.h>
#include <math.h>
#include <stdint.h>

// ---------------- problem constants ----------------
#define NP 16384            // H*W per batch
#define NB 2                // batch
#define PL (NB * NP)        // floats per channel across batch

#define OFF_F      ((size_t)0)
#define OFF_X1     (OFF_F     + (size_t)192  * PL)
#define OFF_MT     (OFF_X1    + (size_t)192  * PL)
#define OFF_OUTD   (OFF_MT    + (size_t)192  * PL)
#define OFF_ATTIN  (OFF_OUTD  + (size_t)384  * PL)
#define OFF_QKV0   (OFF_ATTIN + (size_t)192  * PL)
#define OFF_QKV    (OFF_QKV0  + (size_t)576  * PL)
#define OFF_OUTA   (OFF_QKV   + (size_t)576  * PL)
#define OFF_XMID   (OFF_OUTA  + (size_t)192  * PL)
#define OFF_X2L    (OFF_XMID  + (size_t)192  * PL)
#define OFF_FM     (OFF_X2L   + (size_t)192  * PL)
#define OFF_XIN    (OFF_FM    + (size_t)576  * PL)
#define OFF_DW     (OFF_XIN   + (size_t)1152 * PL)
#define OFF_MT2    (OFF_DW    + (size_t)1152 * PL)
#define OFF_OUT2   (OFF_MT2   + (size_t)576  * PL)
#define OFF_GX     (OFF_OUT2  + (size_t)1152 * PL)
#define OFF_NRM    (OFF_GX    + (size_t)576  * PL)
#define OFF_S      (OFF_NRM   + (size_t)1024)
#define KSPLIT 16
#define SCRATCH_FLOATS (OFF_S + (size_t)KSPLIT * 12288)

__device__ float g_scratch[SCRATCH_FLOATS];

// ================= helpers =================
__device__ __forceinline__ uint32_t smem_u32(const void* p) {
    uint32_t a;
    asm("{ .reg .u64 t; cvta.to.shared.u64 t, %1; cvt.u32.u64 %0, t; }"
        : "=r"(a) : "l"(p));
    return a;
}
__device__ __forceinline__ uint32_t lds32(uint32_t a) {
    uint32_t v;
    asm volatile("ld.shared.b32 %0, [%1];" : "=r"(v) : "r"(a));
    return v;
}
__device__ __forceinline__ void sts128(uint32_t a, uint32_t x, uint32_t y,
                                       uint32_t z, uint32_t w) {
    asm volatile("st.shared.v4.b32 [%0], {%1,%2,%3,%4};"
                 :: "r"(a), "r"(x), "r"(y), "r"(z), "r"(w));
}
__device__ __forceinline__ void mma16816(float c[4], const uint32_t a[4],
                                         const uint32_t b[2]) {
    asm volatile(
        "mma.sync.aligned.m16n8k16.row.col.f32.bf16.bf16.f32 "
        "{%0,%1,%2,%3},{%4,%5,%6,%7},{%8,%9},{%0,%1,%2,%3};"
        : "+f"(c[0]), "+f"(c[1]), "+f"(c[2]), "+f"(c[3])
        : "r"(a[0]), "r"(a[1]), "r"(a[2]), "r"(a[3]), "r"(b[0]), "r"(b[1]));
}
// fp32 pair -> bf16 hi pair + bf16 lo pair (first element in low 16 bits)
__device__ __forceinline__ void hilo2(float v0, float v1, uint32_t& hp, uint32_t& lp) {
    __nv_bfloat16 h0 = __float2bfloat16_rn(v0);
    __nv_bfloat16 h1 = __float2bfloat16_rn(v1);
    float r0 = v0 - __bfloat162float(h0);
    float r1 = v1 - __bfloat162float(h1);
    __nv_bfloat16 l0 = __float2bfloat16_rn(r0);
    __nv_bfloat16 l1 = __float2bfloat16_rn(r1);
    hp = ((uint32_t)__bfloat16_as_ushort(h1) << 16) | __bfloat16_as_ushort(h0);
    lp = ((uint32_t)__bfloat16_as_ushort(l1) << 16) | __bfloat16_as_ushort(l0);
}

// ================= HMMA GEMM =================
// Y[o,p] = sum_k W[o,k]*Acat[k,p] (+epilogue). CTA tile 64(M) x 128(N), BK=32.
// bf16 hi/lo split: D += Ah*Bh + Al*Bh + Ah*Bl  (err ~2^-18).
// 8 warps = 2 (M) x 4 (N); warp tile 32x32. Double-buffered smem.
// Planes per buffer: Ah(64x80B) Al Bh(128x80B) Bl.
#define PLANE_A 5120
#define PLANE_B 10240
#define BUFSZ (2 * PLANE_A + 2 * PLANE_B)   // 30720
#define GSMEM (2 * BUFSZ)                   // 61440

__global__ void __launch_bounds__(256, 2)
hmma_gemm(const float* __restrict__ W, int K,
          const float* __restrict__ A1, int K1, int sA1,
          const float* __restrict__ A2, int sA2,
          int Cout,
          const float* __restrict__ E1, int sE1,
          const float* __restrict__ E2, int sE2,
          float* __restrict__ Y, int sY,
          int mode, int Chalf)
{
    extern __shared__ char smem[];
    const uint32_t sb = smem_u32(smem);
    const int tid = threadIdx.x, wid = tid >> 5, lane = tid & 31;
    const int g = lane >> 2, tig = lane & 3;
    const int wm = wid & 1, wn = wid >> 1;       // 2 M-warps x 4 N-warps
    const int b  = blockIdx.z;
    const int p0 = blockIdx.x * 128;
    const int o0 = blockIdx.y * 64;

    const float* A1b = A1 + (size_t)b * sA1 * NP;
    const float* A2b = A2 ? A2 + (size_t)b * sA2 * NP : A1;

    // loader roles
    const int rowA = tid >> 2, ksegA = (tid & 3) * 8;  // A: 64 rows x 32 k
    const int pB   = tid & 127, halfB = tid >> 7;      // B: pixel, 16-k half
    const float* wrow = W + (size_t)(o0 + rowA) * K;

    uint32_t hA[4], lA[4], hB[8], lB[8];
    auto ldg = [&](int kc) {
        const float* sA = wrow + kc + ksegA;
        float4 f0 = *(const float4*)(sA);
        float4 f1 = *(const float4*)(sA + 4);
        hilo2(f0.x, f0.y, hA[0], lA[0]);
        hilo2(f0.z, f0.w, hA[1], lA[1]);
        hilo2(f1.x, f1.y, hA[2], lA[2]);
        hilo2(f1.z, f1.w, hA[3], lA[3]);
        float vB[16];
#pragma unroll
        for (int kk = 0; kk < 16; kk++) {
            int kg = kc + halfB * 16 + kk;
            const float* s = (kg < K1) ? (A1b + (size_t)kg * NP)
                                       : (A2b + (size_t)(kg - K1) * NP);
            vB[kk] = s[p0 + pB];
        }
#pragma unroll
        for (int j = 0; j < 8; j++) hilo2(vB[2 * j], vB[2 * j + 1], hB[j], lB[j]);
    };
    auto sts = [&](int buf) {
        uint32_t base = sb + buf * BUFSZ;
        uint32_t offA = base + rowA * 80 + ksegA * 2;
        sts128(offA,           hA[0], hA[1], hA[2], hA[3]);
        sts128(offA + PLANE_A, lA[0], lA[1], lA[2], lA[3]);
        uint32_t offB = base + 2 * PLANE_A + pB * 80 + halfB * 32;
        sts128(offB,                hB[0], hB[1], hB[2], hB[3]);
        sts128(offB + 16,           hB[4], hB[5], hB[6], hB[7]);
        sts128(offB + PLANE_B,      lB[0], lB[1], lB[2], lB[3]);
        sts128(offB + PLANE_B + 16, lB[4], lB[5], lB[6], lB[7]);
    };

    float acc[2][4][4];
#pragma unroll
    for (int i = 0; i < 2; i++)
#pragma unroll
        for (int j = 0; j < 4; j++)
#pragma unroll
            for (int q = 0; q < 4; q++) acc[i][j][q] = 0.f;

    const int nch = K >> 5;
    ldg(0);
    sts(0);
    __syncthreads();

    for (int c = 0; c < nch; c++) {
        const bool more = (c + 1 < nch);
        if (more) ldg((c + 1) * 32);

        uint32_t base = sb + (c & 1) * BUFSZ;
        uint32_t ahB = base, alB = base + PLANE_A;
        uint32_t bhB = base + 2 * PLANE_A, blB = bhB + PLANE_B;
#pragma unroll
        for (int s = 0; s < 2; s++) {
            uint32_t ah[2][4], al[2][4];
#pragma unroll
            for (int i = 0; i < 2; i++) {
                uint32_t off = (uint32_t)(wm * 32 + i * 16 + g) * 80 + s * 32 + tig * 4;
                ah[i][0] = lds32(ahB + off);       ah[i][1] = lds32(ahB + off + 640);
                ah[i][2] = lds32(ahB + off + 16);  ah[i][3] = lds32(ahB + off + 656);
                al[i][0] = lds32(alB + off);       al[i][1] = lds32(alB + off + 640);
                al[i][2] = lds32(alB + off + 16);  al[i][3] = lds32(alB + off + 656);
            }
#pragma unroll
            for (int j = 0; j < 4; j++) {
                uint32_t off = (uint32_t)(wn * 32 + j * 8 + g) * 80 + s * 32 + tig * 4;
                uint32_t bh[2], bl[2];
                bh[0] = lds32(bhB + off); bh[1] = lds32(bhB + off + 16);
                bl[0] = lds32(blB + off); bl[1] = lds32(blB + off + 16);
#pragma unroll
                for (int i = 0; i < 2; i++) {
                    mma16816(acc[i][j], ah[i], bh);
                    mma16816(acc[i][j], al[i], bh);
                    mma16816(acc[i][j], ah[i], bl);
                }
            }
        }
        if (more) sts((c + 1) & 1);
        __syncthreads();
    }

    // ---- epilogue ----
    float* Yb = Y + (size_t)b * sY * NP;
    const float* E1b = E1 ? E1 + (size_t)b * sE1 * NP : nullptr;
    const float* E2b = E2 ? E2 + (size_t)b * sE2 * NP : nullptr;
    const int obase = o0 + wm * 32;
    const int pbase = p0 + wn * 32;

    auto emit = [&](int o, int p, float d0, float d1) {
        float y0, y1;
        if (mode == 0) {
            y0 = d0; y1 = d1;
        } else if (mode == 1) {
            const float* e = E1b + (size_t)o * NP + p;
            y0 = d0 + e[0]; y1 = d1 + e[1];
        } else if (mode == 2) {
            const float* br = (o < Chalf) ? (E1b + (size_t)o * NP + p)
                                          : (E2b + (size_t)(o - Chalf) * NP + p);
            y0 = d0 * br[0] + br[0]; y1 = d1 * br[1] + br[1];
        } else {
            const float* e1 = E1b + (size_t)o * NP + p;
            const float* e2 = E2b + (size_t)o * NP + p;
            float r0 = d0 + e1[0], r1 = d1 + e1[1];
            float xg0 = e2[0], xg1 = e2[1];
            float g0 = 0.5f * xg0 * (1.f + erff(xg0 * 0.70710678118654752f));
            float g1 = 0.5f * xg1 * (1.f + erff(xg1 * 0.70710678118654752f));
            y0 = g0 * r0; y1 = g1 * r1;
        }
        *(float2*)(Yb + (size_t)o * NP + p) = make_float2(y0, y1);
    };

#pragma unroll
    for (int i = 0; i < 2; i++) {
#pragma unroll
        for (int j = 0; j < 4; j++) {
            int oA = obase + i * 16 + g;
            int p  = pbase + j * 8 + tig * 2;
            emit(oA,     p, acc[i][j][0], acc[i][j][1]);
            emit(oA + 8, p, acc[i][j][2], acc[i][j][3]);
        }
    }
}

// ---------------- LayerNorm over channel dim ----------------
__global__ void ln_kernel(const float* __restrict__ in, const float* __restrict__ g,
                          const float* __restrict__ be, float* __restrict__ out, int C)
{
    int b = blockIdx.y;
    int p = blockIdx.x * 256 + threadIdx.x;
    const float* ib = in + (size_t)b * C * NP + p;
    float s = 0.f, ss = 0.f;
    for (int c = 0; c < C; c++) {
        float v = ib[(size_t)c * NP];
        s += v; ss += v * v;
    }
    float mu = s / C;
    float var = ss / C - mu * mu;
    float rstd = rsqrtf(var + 1e-5f);
    float* ob = out + (size_t)b * C * NP + p;
    for (int c = 0; c < C; c++) {
        float v = ib[(size_t)c * NP];
        ob[(size_t)c * NP] = (v - mu) * rstd * g[c] + be[c];
    }
}

// ---------------- depthwise 3x3, SAME zero pad ----------------
__global__ void dw_kernel(const float* __restrict__ in, const float* __restrict__ w,
                          float* __restrict__ out, int C)
{
    int b = blockIdx.z, c = blockIdx.y;
    int p = blockIdx.x * 256 + threadIdx.x;
    int y = p >> 7, x = p & 127;
    const float* ib = in + ((size_t)b * C + c) * NP;
    const float* wc = w + c * 9;
    float acc = 0.f;
#pragma unroll
    for (int dy = -1; dy <= 1; dy++) {
        int yy = y + dy;
        if (yy < 0 || yy > 127) continue;
#pragma unroll
        for (int dx = -1; dx <= 1; dx++) {
            int xx = x + dx;
            if (xx < 0 || xx > 127) continue;
            acc = fmaf(ib[yy * 128 + xx], wc[(dy + 1) * 3 + (dx + 1)], acc);
        }
    }
    out[((size_t)b * C + c) * NP + p] = acc;
}

// ---------------- row L2 norms of q,k ----------------
__global__ void norm_kernel(const float* __restrict__ qkv, float* __restrict__ nrm)
{
    int r = blockIdx.x;              // 0..767
    int b = r / 384, c = r % 384;
    const float* src = qkv + ((size_t)b * 576 + c) * NP;
    float s = 0.f;
    for (int i = threadIdx.x; i < NP; i += 256) {
        float v = src[i];
        s += v * v;
    }
    __shared__ float red[256];
    red[threadIdx.x] = s;
    __syncthreads();
    for (int st = 128; st > 0; st >>= 1) {
        if (threadIdx.x < st) red[threadIdx.x] += red[threadIdx.x + st];
        __syncthreads();
    }
    if (threadIdx.x == 0) nrm[r] = fmaxf(sqrtf(red[0]), 1e-12f);
}

// ---------------- attention scores ----------------
__global__ void scores_kernel(const float* __restrict__ qkv, float* __restrict__ S)
{
    int bh = blockIdx.x;
    int ks = blockIdx.y;
    int b = bh / 6, h = bh % 6;
    const float* qb = qkv + ((size_t)b * 576 + h * 32) * NP;
    const float* kb = qkv + ((size_t)b * 576 + 192 + h * 32) * NP;
    __shared__ float qs[32][65], ksm[32][65];
    int tid = threadIdx.x;
    int c = tid >> 3, d0 = (tid & 7) * 4;
    float acc[4] = {0.f, 0.f, 0.f, 0.f};
    int kbase = ks * (NP / KSPLIT);
    for (int t = 0; t < (NP / KSPLIT) / 64; t++) {
        int k0 = kbase + t * 64;
#pragma unroll
        for (int i = 0; i < 8; i++) {
            int e = tid + i * 256;
            int row = e >> 6, col = e & 63;
            qs[row][col]  = qb[(size_t)row * NP + k0 + col];
            ksm[row][col] = kb[(size_t)row * NP + k0 + col];
        }
        __syncthreads();
#pragma unroll
        for (int kk = 0; kk < 64; kk++) {
            float qv = qs[c][kk];
#pragma unroll
            for (int j = 0; j < 4; j++)
                acc[j] = fmaf(qv, ksm[d0 + j][kk], acc[j]);
        }
        __syncthreads();
    }
    float* Sp = S + (size_t)ks * 12288 + bh * 1024 + c * 32 + d0;
#pragma unroll
    for (int j = 0; j < 4; j++) Sp[j] = acc[j];
}

// ---------------- softmax with norm + temperature ----------------
__global__ void softmax_kernel(float* __restrict__ S, const float* __restrict__ nrm,
                               const float* __restrict__ temp)
{
    int bh = blockIdx.y;
    int c  = blockIdx.x;
    int b = bh / 6, h = bh % 6;
    int d = threadIdx.x;
    float acc = 0.f;
    size_t idx = (size_t)bh * 1024 + c * 32 + d;
    for (int j = 0; j < KSPLIT; j++) acc += S[(size_t)j * 12288 + idx];
    float nq = nrm[b * 384 + h * 32 + c];
    float nk = nrm[b * 384 + 192 + h * 32 + d];
    float v = acc / (nq * nk) * temp[h];
    float m = v;
    for (int o = 16; o; o >>= 1) m = fmaxf(m, __shfl_xor_sync(0xffffffffu, m, o));
    float e = expf(v - m);
    float s = e;
    for (int o = 16; o; o >>= 1) s += __shfl_xor_sync(0xffffffffu, s, o);
    S[idx] = e / s;
}

// ---------------- out = attn @ v ----------------
__global__ void av_kernel(const float* __restrict__ S, const float* __restrict__ qkv,
                          float* __restrict__ out)
{
    int b = blockIdx.z, h = blockIdx.y;
    int p = blockIdx.x * 128 + threadIdx.x;
    __shared__ float A[32][32];
    int bh = b * 6 + h;
    for (int i = threadIdx.x; i < 1024; i += 128)
        A[i >> 5][i & 31] = S[(size_t)bh * 1024 + i];
    __syncthreads();
    const float* vb = qkv + ((size_t)b * 576 + 384 + h * 32) * NP + p;
    float vr[32];
#pragma unroll
    for (int d = 0; d < 32; d++) vr[d] = vb[(size_t)d * NP];
    float* ob = out + ((size_t)b * 192 + h * 32) * NP + p;
#pragma unroll
    for (int c = 0; c < 32; c++) {
        float acc = 0.f;
#pragma unroll
        for (int d = 0; d < 32; d++) acc = fmaf(A[c][d], vr[d], acc);
        ob[(size_t)c * NP] = acc;
    }
}

// ---------------- host orchestration ----------------
static inline void launch_gemm(const float* W, int K,
                               const float* A1, int K1, int sA1,
                               const float* A2, int sA2,
                               int Cout,
                               const float* E1, int sE1,
                               const float* E2, int sE2,
                               float* Y, int sY, int mode, int Chalf)
{
    dim3 grid(NP / 128, Cout / 64, NB);
    hmma_gemm<<<grid, 256, GSMEM>>>(W, K, A1, K1, sA1, A2, sA2, Cout,
                                    E1, sE1, E2, sE2, Y, sY, mode, Chalf);
}

extern "C" void kernel_launch(void* const* d_in, const int* in_sizes, int n_in,
                              void* d_out, int out_size)
{
    const float* x       = (const float*)d_in[0];
    const float* feature = (const float*)d_in[1];
    const float* nf_w = (const float*)d_in[2];
    const float* nf_b = (const float*)d_in[3];
    const float* n1_w = (const float*)d_in[4];
    const float* n1_b = (const float*)d_in[5];
    const float* n2_w = (const float*)d_in[6];
    const float* n2_b = (const float*)d_in[7];
    const float* a_cc_w   = (const float*)d_in[8];
    const float* a_fus_w  = (const float*)d_in[9];
    const float* a_msk_w  = (const float*)d_in[10];
    const float* a_qkv_w  = (const float*)d_in[11];
    const float* a_qkvdw  = (const float*)d_in[12];
    const float* a_temp   = (const float*)d_in[13];
    const float* a_proj_w = (const float*)d_in[14];
    const float* f_pm_w   = (const float*)d_in[15];
    const float* f_pi_w   = (const float*)d_in[16];
    const float* f_dw_w   = (const float*)d_in[17];
    const float* f_cc_w   = (const float*)d_in[18];
    const float* f_fus_w  = (const float*)d_in[19];
    const float* f_msk_w  = (const float*)d_in[20];
    const float* f_po_w   = (const float*)d_in[21];
    float* out = (float*)d_out;

    cudaFuncSetAttribute(hmma_gemm, cudaFuncAttributeMaxDynamicSharedMemorySize, GSMEM);

    float* base = nullptr;
    cudaGetSymbolAddress((void**)&base, g_scratch);
    float* F     = base + OFF_F;
    float* X1    = base + OFF_X1;
    float* MT    = base + OFF_MT;
    float* OUTD  = base + OFF_OUTD;
    float* ATTIN = base + OFF_ATTIN;
    float* QKV0  = base + OFF_QKV0;
    float* QKV   = base + OFF_QKV;
    float* OUTA  = base + OFF_OUTA;
    float* XMID  = base + OFF_XMID;
    float* X2L   = base + OFF_X2L;
    float* FM    = base + OFF_FM;
    float* XIN   = base + OFF_XIN;
    float* DW    = base + OFF_DW;
    float* MT2   = base + OFF_MT2;
    float* OUT2  = base + OFF_OUT2;
    float* GX    = base + OFF_GX;
    float* NRM   = base + OFF_NRM;
    float* S     = base + OFF_S;

    dim3 lng(NP / 256, NB);

    ln_kernel<<<lng, 256>>>(feature, nf_w, nf_b, F, 192);
    ln_kernel<<<lng, 256>>>(x, n1_w, n1_b, X1, 192);

    // --- attention DDF ---
    launch_gemm(a_msk_w, 192, F, 192, 192, nullptr, 0, 192,
                nullptr, 0, nullptr, 0, MT, 192, 0, 0);
    launch_gemm(a_cc_w, 384, X1, 192, 192, MT, 192, 384,
                X1, 192, MT, 192, OUTD, 384, 2, 192);
    launch_gemm(a_fus_w, 384, OUTD, 384, 384, nullptr, 0, 192,
                X1, 192, nullptr, 0, ATTIN, 192, 1, 0);

    // qkv + depthwise
    launch_gemm(a_qkv_w, 192, ATTIN, 192, 192, nullptr, 0, 576,
                nullptr, 0, nullptr, 0, QKV0, 576, 0, 0);
    dw_kernel<<<dim3(NP / 256, 576, NB), 256>>>(QKV0, a_qkvdw, QKV, 576);

    // channel attention
    norm_kernel<<<768, 256>>>(QKV, NRM);
    scores_kernel<<<dim3(12, KSPLIT), 256>>>(QKV, S);
    softmax_kernel<<<dim3(32, 12), 32>>>(S, NRM, a_temp);
    av_kernel<<<dim3(NP / 128, 6, NB), 128>>>(S, QKV, OUTA);

    // proj + residual with original x
    launch_gemm(a_proj_w, 192, OUTA, 192, 192, nullptr, 0, 192,
                x, 192, nullptr, 0, XMID, 192, 1, 0);

    // --- FFN ---
    ln_kernel<<<lng, 256>>>(XMID, n2_w, n2_b, X2L, 192);
    launch_gemm(f_pm_w, 192, F, 192, 192, nullptr, 0, 576,
                nullptr, 0, nullptr, 0, FM, 576, 0, 0);
    launch_gemm(f_pi_w, 192, X2L, 192, 192, nullptr, 0, 1152,
                nullptr, 0, nullptr, 0, XIN, 1152, 0, 0);
    dw_kernel<<<dim3(NP / 256, 1152, NB), 256>>>(XIN, f_dw_w, DW, 1152);

    const float* X2H = DW + (size_t)576 * NP;
    launch_gemm(f_msk_w, 576, FM, 576, 576, nullptr, 0, 576,
                nullptr, 0, nullptr, 0, MT2, 576, 0, 0);
    launch_gemm(f_cc_w, 1152, X2H, 576, 1152, MT2, 576, 1152,
                X2H, 1152, MT2, 576, OUT2, 1152, 2, 576);
    launch_gemm(f_fus_w, 1152, OUT2, 1152, 1152, nullptr, 0, 576,
                X2H, 1152, DW, 1152, GX, 576, 3, 0);
    launch_gemm(f_po_w, 576, GX, 576, 576, nullptr, 0, 192,
                XMID, 192, nullptr, 0, out, 192, 1, 0);
}

// round 6
// speedup vs baseline: 2.4031x; 1.0311x over previous
#include <cuda_runtime.h>
#include <cuda_bf16.h>
#include <math.h>
#include <stdint.h>

// ---------------- problem constants ----------------
#define NP 16384            // H*W per batch
#define NB 2                // batch
#define PL (NB * NP)        // floats per channel across batch

#define OFF_F      ((size_t)0)
#define OFF_X1     (OFF_F     + (size_t)192  * PL)
#define OFF_MT     (OFF_X1    + (size_t)192  * PL)
#define OFF_OUTD   (OFF_MT    + (size_t)192  * PL)
#define OFF_ATTIN  (OFF_OUTD  + (size_t)384  * PL)
#define OFF_QKV0   (OFF_ATTIN + (size_t)192  * PL)
#define OFF_QKV    (OFF_QKV0  + (size_t)576  * PL)
#define OFF_OUTA   (OFF_QKV   + (size_t)576  * PL)
#define OFF_XMID   (OFF_OUTA  + (size_t)192  * PL)
#define OFF_X2L    (OFF_XMID  + (size_t)192  * PL)
#define OFF_FM     (OFF_X2L   + (size_t)192  * PL)
#define OFF_XIN    (OFF_FM    + (size_t)576  * PL)
#define OFF_DW     (OFF_XIN   + (size_t)1152 * PL)
#define OFF_MT2    (OFF_DW    + (size_t)1152 * PL)
#define OFF_OUT2   (OFF_MT2   + (size_t)576  * PL)
#define OFF_GX     (OFF_OUT2  + (size_t)1152 * PL)
#define OFF_NRM    (OFF_GX    + (size_t)576  * PL)
#define OFF_S      (OFF_NRM   + (size_t)1024)
#define KSPLIT 16
#define SCRATCH_FLOATS (OFF_S + (size_t)KSPLIT * 12288)

__device__ float g_scratch[SCRATCH_FLOATS];

// ================= helpers =================
__device__ __forceinline__ uint32_t smem_u32(const void* p) {
    uint32_t a;
    asm("{ .reg .u64 t; cvta.to.shared.u64 t, %1; cvt.u32.u64 %0, t; }"
        : "=r"(a) : "l"(p));
    return a;
}
__device__ __forceinline__ void ldsm4(uint32_t r[4], uint32_t a) {
    asm volatile("ldmatrix.sync.aligned.m8n8.x4.shared.b16 {%0,%1,%2,%3}, [%4];"
                 : "=r"(r[0]), "=r"(r[1]), "=r"(r[2]), "=r"(r[3]) : "r"(a));
}
__device__ __forceinline__ void sts128(uint32_t a, uint32_t x, uint32_t y,
                                       uint32_t z, uint32_t w) {
    asm volatile("st.shared.v4.b32 [%0], {%1,%2,%3,%4};"
                 :: "r"(a), "r"(x), "r"(y), "r"(z), "r"(w));
}
__device__ __forceinline__ void mma16816(float c[4], const uint32_t a[4],
                                         const uint32_t b[2]) {
    asm volatile(
        "mma.sync.aligned.m16n8k16.row.col.f32.bf16.bf16.f32 "
        "{%0,%1,%2,%3},{%4,%5,%6,%7},{%8,%9},{%0,%1,%2,%3};"
        : "+f"(c[0]), "+f"(c[1]), "+f"(c[2]), "+f"(c[3])
        : "r"(a[0]), "r"(a[1]), "r"(a[2]), "r"(a[3]), "r"(b[0]), "r"(b[1]));
}
// fp32 pair -> bf16 hi pair + bf16 lo pair (first element in low 16 bits)
__device__ __forceinline__ void hilo2(float v0, float v1, uint32_t& hp, uint32_t& lp) {
    __nv_bfloat16 h0 = __float2bfloat16_rn(v0);
    __nv_bfloat16 h1 = __float2bfloat16_rn(v1);
    float r0 = v0 - __bfloat162float(h0);
    float r1 = v1 - __bfloat162float(h1);
    __nv_bfloat16 l0 = __float2bfloat16_rn(r0);
    __nv_bfloat16 l1 = __float2bfloat16_rn(r1);
    hp = ((uint32_t)__bfloat16_as_ushort(h1) << 16) | __bfloat16_as_ushort(h0);
    lp = ((uint32_t)__bfloat16_as_ushort(l1) << 16) | __bfloat16_as_ushort(l0);
}

// ================= HMMA GEMM =================
// Y[o,p] = sum_k W[o,k]*Acat[k,p] (+epilogue). CTA tile 64(M) x 128(N), BK=32.
// bf16 hi/lo split: D += Ah*Bh + Al*Bh + Ah*Bl  (err ~2^-18).
// 8 warps = 2 (M) x 4 (N); warp tile 32x32. Double-buffered smem. ldmatrix frags.
#define PLANE_A 5120
#define PLANE_B 10240
#define BUFSZ (2 * PLANE_A + 2 * PLANE_B)   // 30720
#define GSMEM (2 * BUFSZ)                   // 61440

__global__ void __launch_bounds__(256, 2)
hmma_gemm(const float* __restrict__ W, int K,
          const float* __restrict__ A1, int K1, int sA1,
          const float* __restrict__ A2, int sA2,
          int Cout,
          const float* __restrict__ E1, int sE1,
          const float* __restrict__ E2, int sE2,
          float* __restrict__ Y, int sY,
          int mode, int Chalf)
{
    extern __shared__ char smem[];
    const uint32_t sb = smem_u32(smem);
    const int tid = threadIdx.x, wid = tid >> 5, lane = tid & 31;
    const int g = lane >> 2, tig = lane & 3;
    const int wm = wid & 1, wn = wid >> 1;       // 2 M-warps x 4 N-warps
    const int b  = blockIdx.z;
    const int p0 = blockIdx.x * 128;
    const int o0 = blockIdx.y * 64;

    const float* A1b = A1 + (size_t)b * sA1 * NP;
    const float* A2b = A2 ? A2 + (size_t)b * sA2 * NP : A1;

    // loader roles
    const int rowA = tid >> 2, ksegA = (tid & 3) * 8;  // A: 64 rows x 32 k
    const int pB   = tid & 127, halfB = tid >> 7;      // B: pixel, 16-k half
    const float* wrow = W + (size_t)(o0 + rowA) * K;

    // ldmatrix lane-relative offsets
    //  A-type (16x16 tile): lane -> (lane%16)*80 + (lane/16)*16
    const uint32_t offAt = (uint32_t)(lane & 15) * 80 + (uint32_t)(lane >> 4) * 16
                         + (uint32_t)(wm * 32) * 80;
    //  B-type (x4 covering j,j+1): lane -> ((lane>>4)*8 + (lane&7))*80 + ((lane>>3)&1)*16
    const uint32_t offBt = (uint32_t)((lane >> 4) * 8 + (lane & 7)) * 80
                         + (uint32_t)((lane >> 3) & 1) * 16
                         + (uint32_t)(wn * 32) * 80;

    uint32_t hA[4], lA[4], hB[8], lB[8];
    auto ldg = [&](int kc) {
        const float* sA = wrow + kc + ksegA;
        float4 f0 = *(const float4*)(sA);
        float4 f1 = *(const float4*)(sA + 4);
        hilo2(f0.x, f0.y, hA[0], lA[0]);
        hilo2(f0.z, f0.w, hA[1], lA[1]);
        hilo2(f1.x, f1.y, hA[2], lA[2]);
        hilo2(f1.z, f1.w, hA[3], lA[3]);
        float vB[16];
#pragma unroll
        for (int kk = 0; kk < 16; kk++) {
            int kg = kc + halfB * 16 + kk;
            const float* s = (kg < K1) ? (A1b + (size_t)kg * NP)
                                       : (A2b + (size_t)(kg - K1) * NP);
            vB[kk] = s[p0 + pB];
        }
#pragma unroll
        for (int j = 0; j < 8; j++) hilo2(vB[2 * j], vB[2 * j + 1], hB[j], lB[j]);
    };
    auto sts = [&](int buf) {
        uint32_t base = sb + buf * BUFSZ;
        uint32_t offA = base + rowA * 80 + ksegA * 2;
        sts128(offA,           hA[0], hA[1], hA[2], hA[3]);
        sts128(offA + PLANE_A, lA[0], lA[1], lA[2], lA[3]);
        uint32_t offB = base + 2 * PLANE_A + pB * 80 + halfB * 32;
        sts128(offB,                hB[0], hB[1], hB[2], hB[3]);
        sts128(offB + 16,           hB[4], hB[5], hB[6], hB[7]);
        sts128(offB + PLANE_B,      lB[0], lB[1], lB[2], lB[3]);
        sts128(offB + PLANE_B + 16, lB[4], lB[5], lB[6], lB[7]);
    };

    float acc[2][4][4];
#pragma unroll
    for (int i = 0; i < 2; i++)
#pragma unroll
        for (int j = 0; j < 4; j++)
#pragma unroll
            for (int q = 0; q < 4; q++) acc[i][j][q] = 0.f;

    const int nch = K >> 5;
    ldg(0);
    sts(0);
    __syncthreads();

    for (int c = 0; c < nch; c++) {
        const bool more = (c + 1 < nch);
        if (more) ldg((c + 1) * 32);

        uint32_t base = sb + (c & 1) * BUFSZ;
        uint32_t ahB = base + offAt, alB = ahB + PLANE_A;
        uint32_t bhB = base + 2 * PLANE_A + offBt, blB = bhB + PLANE_B;
#pragma unroll
        for (int s = 0; s < 2; s++) {
            uint32_t ah[2][4], al[2][4], bh[2][4], bl[2][4];
#pragma unroll
            for (int i = 0; i < 2; i++) {
                ldsm4(ah[i], ahB + i * (16 * 80) + s * 32);
                ldsm4(al[i], alB + i * (16 * 80) + s * 32);
            }
#pragma unroll
            for (int q = 0; q < 2; q++) {
                ldsm4(bh[q], bhB + q * (16 * 80) + s * 32);
                ldsm4(bl[q], blB + q * (16 * 80) + s * 32);
            }
#pragma unroll
            for (int q = 0; q < 2; q++) {
#pragma unroll
                for (int jj = 0; jj < 2; jj++) {
                    int j = q * 2 + jj;
                    const uint32_t* bhf = &bh[q][jj * 2];
                    const uint32_t* blf = &bl[q][jj * 2];
#pragma unroll
                    for (int i = 0; i < 2; i++) {
                        mma16816(acc[i][j], ah[i], bhf);
                        mma16816(acc[i][j], al[i], bhf);
                        mma16816(acc[i][j], ah[i], blf);
                    }
                }
            }
        }
        if (more) sts((c + 1) & 1);
        __syncthreads();
    }

    // ---- epilogue ----
    float* Yb = Y + (size_t)b * sY * NP;
    const float* E1b = E1 ? E1 + (size_t)b * sE1 * NP : nullptr;
    const float* E2b = E2 ? E2 + (size_t)b * sE2 * NP : nullptr;
    const int obase = o0 + wm * 32;
    const int pbase = p0 + wn * 32;

    auto emit = [&](int o, int p, float d0, float d1) {
        float y0, y1;
        if (mode == 0) {
            y0 = d0; y1 = d1;
        } else if (mode == 1) {
            const float* e = E1b + (size_t)o * NP + p;
            y0 = d0 + e[0]; y1 = d1 + e[1];
        } else if (mode == 2) {
            const float* br = (o < Chalf) ? (E1b + (size_t)o * NP + p)
                                          : (E2b + (size_t)(o - Chalf) * NP + p);
            y0 = d0 * br[0] + br[0]; y1 = d1 * br[1] + br[1];
        } else {
            const float* e1 = E1b + (size_t)o * NP + p;
            const float* e2 = E2b + (size_t)o * NP + p;
            float r0 = d0 + e1[0], r1 = d1 + e1[1];
            float xg0 = e2[0], xg1 = e2[1];
            float g0 = 0.5f * xg0 * (1.f + erff(xg0 * 0.70710678118654752f));
            float g1 = 0.5f * xg1 * (1.f + erff(xg1 * 0.70710678118654752f));
            y0 = g0 * r0; y1 = g1 * r1;
        }
        *(float2*)(Yb + (size_t)o * NP + p) = make_float2(y0, y1);
    };

#pragma unroll
    for (int i = 0; i < 2; i++) {
#pragma unroll
        for (int j = 0; j < 4; j++) {
            int oA = obase + i * 16 + g;
            int p  = pbase + j * 8 + tig * 2;
            emit(oA,     p, acc[i][j][0], acc[i][j][1]);
            emit(oA + 8, p, acc[i][j][2], acc[i][j][3]);
        }
    }
}

// ---------------- LayerNorm over channel dim ----------------
__global__ void ln_kernel(const float* __restrict__ in, const float* __restrict__ g,
                          const float* __restrict__ be, float* __restrict__ out, int C)
{
    int b = blockIdx.y;
    int p = blockIdx.x * 256 + threadIdx.x;
    const float* ib = in + (size_t)b * C * NP + p;
    float s = 0.f, ss = 0.f;
    for (int c = 0; c < C; c++) {
        float v = ib[(size_t)c * NP];
        s += v; ss += v * v;
    }
    float mu = s / C;
    float var = ss / C - mu * mu;
    float rstd = rsqrtf(var + 1e-5f);
    float* ob = out + (size_t)b * C * NP + p;
    for (int c = 0; c < C; c++) {
        float v = ib[(size_t)c * NP];
        ob[(size_t)c * NP] = (v - mu) * rstd * g[c] + be[c];
    }
}

// ---------------- depthwise 3x3, SAME zero pad ----------------
__global__ void dw_kernel(const float* __restrict__ in, const float* __restrict__ w,
                          float* __restrict__ out, int C)
{
    int b = blockIdx.z, c = blockIdx.y;
    int p = blockIdx.x * 256 + threadIdx.x;
    int y = p >> 7, x = p & 127;
    const float* ib = in + ((size_t)b * C + c) * NP;
    const float* wc = w + c * 9;
    float acc = 0.f;
#pragma unroll
    for (int dy = -1; dy <= 1; dy++) {
        int yy = y + dy;
        if (yy < 0 || yy > 127) continue;
#pragma unroll
        for (int dx = -1; dx <= 1; dx++) {
            int xx = x + dx;
            if (xx < 0 || xx > 127) continue;
            acc = fmaf(ib[yy * 128 + xx], wc[(dy + 1) * 3 + (dx + 1)], acc);
        }
    }
    out[((size_t)b * C + c) * NP + p] = acc;
}

// ---------------- row L2 norms of q,k ----------------
__global__ void norm_kernel(const float* __restrict__ qkv, float* __restrict__ nrm)
{
    int r = blockIdx.x;              // 0..767
    int b = r / 384, c = r % 384;
    const float* src = qkv + ((size_t)b * 576 + c) * NP;
    float s = 0.f;
    for (int i = threadIdx.x; i < NP; i += 256) {
        float v = src[i];
        s += v * v;
    }
    __shared__ float red[256];
    red[threadIdx.x] = s;
    __syncthreads();
    for (int st = 128; st > 0; st >>= 1) {
        if (threadIdx.x < st) red[threadIdx.x] += red[threadIdx.x + st];
        __syncthreads();
    }
    if (threadIdx.x == 0) nrm[r] = fmaxf(sqrtf(red[0]), 1e-12f);
}

// ---------------- attention scores ----------------
__global__ void scores_kernel(const float* __restrict__ qkv, float* __restrict__ S)
{
    int bh = blockIdx.x;
    int ks = blockIdx.y;
    int b = bh / 6, h = bh % 6;
    const float* qb = qkv + ((size_t)b * 576 + h * 32) * NP;
    const float* kb = qkv + ((size_t)b * 576 + 192 + h * 32) * NP;
    __shared__ float qs[32][65], ksm[32][65];
    int tid = threadIdx.x;
    int c = tid >> 3, d0 = (tid & 7) * 4;
    float acc[4] = {0.f, 0.f, 0.f, 0.f};
    int kbase = ks * (NP / KSPLIT);
    for (int t = 0; t < (NP / KSPLIT) / 64; t++) {
        int k0 = kbase + t * 64;
#pragma unroll
        for (int i = 0; i < 8; i++) {
            int e = tid + i * 256;
            int row = e >> 6, col = e & 63;
            qs[row][col]  = qb[(size_t)row * NP + k0 + col];
            ksm[row][col] = kb[(size_t)row * NP + k0 + col];
        }
        __syncthreads();
#pragma unroll
        for (int kk = 0; kk < 64; kk++) {
            float qv = qs[c][kk];
#pragma unroll
            for (int j = 0; j < 4; j++)
                acc[j] = fmaf(qv, ksm[d0 + j][kk], acc[j]);
        }
        __syncthreads();
    }
    float* Sp = S + (size_t)ks * 12288 + bh * 1024 + c * 32 + d0;
#pragma unroll
    for (int j = 0; j < 4; j++) Sp[j] = acc[j];
}

// ---------------- softmax with norm + temperature ----------------
__global__ void softmax_kernel(float* __restrict__ S, const float* __restrict__ nrm,
                               const float* __restrict__ temp)
{
    int bh = blockIdx.y;
    int c  = blockIdx.x;
    int b = bh / 6, h = bh % 6;
    int d = threadIdx.x;
    float acc = 0.f;
    size_t idx = (size_t)bh * 1024 + c * 32 + d;
    for (int j = 0; j < KSPLIT; j++) acc += S[(size_t)j * 12288 + idx];
    float nq = nrm[b * 384 + h * 32 + c];
    float nk = nrm[b * 384 + 192 + h * 32 + d];
    float v = acc / (nq * nk) * temp[h];
    float m = v;
    for (int o = 16; o; o >>= 1) m = fmaxf(m, __shfl_xor_sync(0xffffffffu, m, o));
    float e = expf(v - m);
    float s = e;
    for (int o = 16; o; o >>= 1) s += __shfl_xor_sync(0xffffffffu, s, o);
    S[idx] = e / s;
}

// ---------------- out = attn @ v ----------------
__global__ void av_kernel(const float* __restrict__ S, const float* __restrict__ qkv,
                          float* __restrict__ out)
{
    int b = blockIdx.z, h = blockIdx.y;
    int p = blockIdx.x * 128 + threadIdx.x;
    __shared__ float A[32][32];
    int bh = b * 6 + h;
    for (int i = threadIdx.x; i < 1024; i += 128)
        A[i >> 5][i & 31] = S[(size_t)bh * 1024 + i];
    __syncthreads();
    const float* vb = qkv + ((size_t)b * 576 + 384 + h * 32) * NP + p;
    float vr[32];
#pragma unroll
    for (int d = 0; d < 32; d++) vr[d] = vb[(size_t)d * NP];
    float* ob = out + ((size_t)b * 192 + h * 32) * NP + p;
#pragma unroll
    for (int c = 0; c < 32; c++) {
        float acc = 0.f;
#pragma unroll
        for (int d = 0; d < 32; d++) acc = fmaf(A[c][d], vr[d], acc);
        ob[(size_t)c * NP] = acc;
    }
}

// ---------------- host orchestration ----------------
static inline void launch_gemm(const float* W, int K,
                               const float* A1, int K1, int sA1,
                               const float* A2, int sA2,
                               int Cout,
                               const float* E1, int sE1,
                               const float* E2, int sE2,
                               float* Y, int sY, int mode, int Chalf)
{
    dim3 grid(NP / 128, Cout / 64, NB);
    hmma_gemm<<<grid, 256, GSMEM>>>(W, K, A1, K1, sA1, A2, sA2, Cout,
                                    E1, sE1, E2, sE2, Y, sY, mode, Chalf);
}

extern "C" void kernel_launch(void* const* d_in, const int* in_sizes, int n_in,
                              void* d_out, int out_size)
{
    const float* x       = (const float*)d_in[0];
    const float* feature = (const float*)d_in[1];
    const float* nf_w = (const float*)d_in[2];
    const float* nf_b = (const float*)d_in[3];
    const float* n1_w = (const float*)d_in[4];
    const float* n1_b = (const float*)d_in[5];
    const float* n2_w = (const float*)d_in[6];
    const float* n2_b = (const float*)d_in[7];
    const float* a_cc_w   = (const float*)d_in[8];
    const float* a_fus_w  = (const float*)d_in[9];
    const float* a_msk_w  = (const float*)d_in[10];
    const float* a_qkv_w  = (const float*)d_in[11];
    const float* a_qkvdw  = (const float*)d_in[12];
    const float* a_temp   = (const float*)d_in[13];
    const float* a_proj_w = (const float*)d_in[14];
    const float* f_pm_w   = (const float*)d_in[15];
    const float* f_pi_w   = (const float*)d_in[16];
    const float* f_dw_w   = (const float*)d_in[17];
    const float* f_cc_w   = (const float*)d_in[18];
    const float* f_fus_w  = (const float*)d_in[19];
    const float* f_msk_w  = (const float*)d_in[20];
    const float* f_po_w   = (const float*)d_in[21];
    float* out = (float*)d_out;

    cudaFuncSetAttribute(hmma_gemm, cudaFuncAttributeMaxDynamicSharedMemorySize, GSMEM);

    float* base = nullptr;
    cudaGetSymbolAddress((void**)&base, g_scratch);
    float* F     = base + OFF_F;
    float* X1    = base + OFF_X1;
    float* MT    = base + OFF_MT;
    float* OUTD  = base + OFF_OUTD;
    float* ATTIN = base + OFF_ATTIN;
    float* QKV0  = base + OFF_QKV0;
    float* QKV   = base + OFF_QKV;
    float* OUTA  = base + OFF_OUTA;
    float* XMID  = base + OFF_XMID;
    float* X2L   = base + OFF_X2L;
    float* FM    = base + OFF_FM;
    float* XIN   = base + OFF_XIN;
    float* DW    = base + OFF_DW;
    float* MT2   = base + OFF_MT2;
    float* OUT2  = base + OFF_OUT2;
    float* GX    = base + OFF_GX;
    float* NRM   = base + OFF_NRM;
    float* S     = base + OFF_S;

    dim3 lng(NP / 256, NB);

    ln_kernel<<<lng, 256>>>(feature, nf_w, nf_b, F, 192);
    ln_kernel<<<lng, 256>>>(x, n1_w, n1_b, X1, 192);

    // --- attention DDF ---
    launch_gemm(a_msk_w, 192, F, 192, 192, nullptr, 0, 192,
                nullptr, 0, nullptr, 0, MT, 192, 0, 0);
    launch_gemm(a_cc_w, 384, X1, 192, 192, MT, 192, 384,
                X1, 192, MT, 192, OUTD, 384, 2, 192);
    launch_gemm(a_fus_w, 384, OUTD, 384, 384, nullptr, 0, 192,
                X1, 192, nullptr, 0, ATTIN, 192, 1, 0);

    // qkv + depthwise
    launch_gemm(a_qkv_w, 192, ATTIN, 192, 192, nullptr, 0, 576,
                nullptr, 0, nullptr, 0, QKV0, 576, 0, 0);
    dw_kernel<<<dim3(NP / 256, 576, NB), 256>>>(QKV0, a_qkvdw, QKV, 576);

    // channel attention
    norm_kernel<<<768, 256>>>(QKV, NRM);
    scores_kernel<<<dim3(12, KSPLIT), 256>>>(QKV, S);
    softmax_kernel<<<dim3(32, 12), 32>>>(S, NRM, a_temp);
    av_kernel<<<dim3(NP / 128, 6, NB), 128>>>(S, QKV, OUTA);

    // proj + residual with original x
    launch_gemm(a_proj_w, 192, OUTA, 192, 192, nullptr, 0, 192,
                x, 192, nullptr, 0, XMID, 192, 1, 0);

    // --- FFN ---
    ln_kernel<<<lng, 256>>>(XMID, n2_w, n2_b, X2L, 192);
    launch_gemm(f_pm_w, 192, F, 192, 192, nullptr, 0, 576,
                nullptr, 0, nullptr, 0, FM, 576, 0, 0);
    launch_gemm(f_pi_w, 192, X2L, 192, 192, nullptr, 0, 1152,
                nullptr, 0, nullptr, 0, XIN, 1152, 0, 0);
    dw_kernel<<<dim3(NP / 256, 1152, NB), 256>>>(XIN, f_dw_w, DW, 1152);

    const float* X2H = DW + (size_t)576 * NP;
    launch_gemm(f_msk_w, 576, FM, 576, 576, nullptr, 0, 576,
                nullptr, 0, nullptr, 0, MT2, 576, 0, 0);
    launch_gemm(f_cc_w, 1152, X2H, 576, 1152, MT2, 576, 1152,
                X2H, 1152, MT2, 576, OUT2, 1152, 2, 576);
    launch_gemm(f_fus_w, 1152, OUT2, 1152, 1152, nullptr, 0, 576,
                X2H, 1152, DW, 1152, GX, 576, 3, 0);
    launch_gemm(f_po_w, 576, GX, 576, 576, nullptr, 0, 192,
                XMID, 192, nullptr, 0, out, 192, 1, 0);
}

// round 7
// speedup vs baseline: 3.0868x; 1.2845x over previous
#include <cuda_runtime.h>
#include <cuda_bf16.h>
#include <math.h>
#include <stdint.h>

// ---------------- problem constants ----------------
#define NP 16384            // H*W per batch
#define NB 2
#define PL (NB * NP)        // elems per channel (both batches)
#define KSPLIT 16

// ---- channel offsets inside the hi/lo mega-planes ----
#define CH_X     0
#define CH_F     192
#define CH_X1    384
#define CH_MT    576
#define CH_OUTD  768
#define CH_ATTIN 1152
#define CH_QKV0  1344
#define CH_QKV   1920
#define CH_OUTA  2496
#define CH_XMID  2688
#define CH_X2L   2880
#define CH_FM    3072
#define CH_XIN   3648
#define CH_DW    4800
#define CH_X2H   5376      // CH_DW + 576
#define CH_MT2   5952
#define CH_OUT2  6528
#define CH_GX    7680
#define CH_TOT   8256

__device__ __nv_bfloat16 g_hi[(size_t)CH_TOT * PL];
__device__ __nv_bfloat16 g_lo[(size_t)CH_TOT * PL];

// ---- weight offsets ----
#define WO_AMSK  0
#define WO_ACC   36864
#define WO_AFUS  184320
#define WO_AQKV  258048
#define WO_APROJ 368640
#define WO_FPM   405504
#define WO_FPI   516096
#define WO_FMSK  737280
#define WO_FCC   1069056
#define WO_FFUS  2396160
#define WO_FPO   3059712
#define WTOT     3170304
__device__ __nv_bfloat16 g_whi[WTOT];
__device__ __nv_bfloat16 g_wlo[WTOT];

__device__ float g_f32[1024 + KSPLIT * 12288];   // NRM(768) + S partials

// ================= helpers =================
__device__ __forceinline__ uint32_t smem_u32(const void* p) {
    uint32_t a;
    asm("{ .reg .u64 t; cvta.to.shared.u64 t, %1; cvt.u32.u64 %0, t; }"
        : "=r"(a) : "l"(p));
    return a;
}
__device__ __forceinline__ void ldsm4(uint32_t r[4], uint32_t a) {
    asm volatile("ldmatrix.sync.aligned.m8n8.x4.shared.b16 {%0,%1,%2,%3}, [%4];"
                 : "=r"(r[0]), "=r"(r[1]), "=r"(r[2]), "=r"(r[3]) : "r"(a));
}
__device__ __forceinline__ void ldsm4t(uint32_t r[4], uint32_t a) {
    asm volatile("ldmatrix.sync.aligned.m8n8.x4.trans.shared.b16 {%0,%1,%2,%3}, [%4];"
                 : "=r"(r[0]), "=r"(r[1]), "=r"(r[2]), "=r"(r[3]) : "r"(a));
}
__device__ __forceinline__ void cpasync16(uint32_t s, const void* g) {
    asm volatile("cp.async.ca.shared.global [%0], [%1], 16;" :: "r"(s), "l"(g));
}
#define CP_COMMIT() asm volatile("cp.async.commit_group;" ::: "memory")
#define CP_WAIT0()  asm volatile("cp.async.wait_group 0;" ::: "memory")

__device__ __forceinline__ void mma16816(float c[4], const uint32_t a[4],
                                         const uint32_t b[2]) {
    asm volatile(
        "mma.sync.aligned.m16n8k16.row.col.f32.bf16.bf16.f32 "
        "{%0,%1,%2,%3},{%4,%5,%6,%7},{%8,%9},{%0,%1,%2,%3};"
        : "+f"(c[0]), "+f"(c[1]), "+f"(c[2]), "+f"(c[3])
        : "r"(a[0]), "r"(a[1]), "r"(a[2]), "r"(a[3]), "r"(b[0]), "r"(b[1]));
}
__device__ __forceinline__ float b2f(__nv_bfloat16 v) {
    return __uint_as_float(((uint32_t)__bfloat16_as_ushort(v)) << 16);
}
__device__ __forceinline__ float rdhl(size_t idx) {
    return b2f(g_hi[idx]) + b2f(g_lo[idx]);
}
__device__ __forceinline__ void wrhl(size_t idx, float v) {
    __nv_bfloat16 h = __float2bfloat16_rn(v);
    g_hi[idx] = h;
    g_lo[idx] = __float2bfloat16_rn(v - b2f(h));
}
// fp32 pair -> packed bf16 hi pair + lo pair (first elem in low bits)
__device__ __forceinline__ void hilo2(float v0, float v1, uint32_t& hp, uint32_t& lp) {
    __nv_bfloat16 h0 = __float2bfloat16_rn(v0);
    __nv_bfloat16 h1 = __float2bfloat16_rn(v1);
    float r0 = v0 - b2f(h0), r1 = v1 - b2f(h1);
    __nv_bfloat16 l0 = __float2bfloat16_rn(r0);
    __nv_bfloat16 l1 = __float2bfloat16_rn(r1);
    hp = ((uint32_t)__bfloat16_as_ushort(h1) << 16) | __bfloat16_as_ushort(h0);
    lp = ((uint32_t)__bfloat16_as_ushort(l1) << 16) | __bfloat16_as_ushort(l0);
}

// ================= converters =================
__global__ void cvt_w(const float* __restrict__ src, size_t dst, int n) {
    int i = blockIdx.x * 256 + threadIdx.x;
    if (i < n) {
        float v = src[i];
        __nv_bfloat16 h = __float2bfloat16_rn(v);
        g_whi[dst + i] = h;
        g_wlo[dst + i] = __float2bfloat16_rn(v - b2f(h));
    }
}
__global__ void cvt_act(const float* __restrict__ src, int C, size_t chBase) {
    int b = blockIdx.z, c = blockIdx.y;
    int p = blockIdx.x * 256 + threadIdx.x;
    float v = src[((size_t)b * C + c) * NP + p];
    wrhl((chBase + c) * (size_t)PL + (size_t)b * NP + p, v);
}

// ================= HMMA GEMM (cp.async + hi/lo planes) =================
// CTA tile 64(M) x 256(N), BK=32, 8 warps 2(M)x4(N), warp tile 32x64.
#define SMA_ROW 80
#define PL_A 5120              // 64*80
#define SMB_ROW 528
#define PL_B 16896             // 32*528
#define SOFF_B 10240           // 2*PL_A
#define BUFSZ 44032
#define GSMEM 88064

__global__ void __launch_bounds__(256, 2)
hmma_gemm(size_t wOff, int K, size_t aOff1, int K1, size_t aOff2,
          int Cout, size_t e1Off, size_t e2Off, size_t yOff,
          int mode, int Chalf, float* __restrict__ Yf)
{
    extern __shared__ char smem[];
    const uint32_t sb = smem_u32(smem);
    const int tid = threadIdx.x, wid = tid >> 5, lane = tid & 31;
    const int g = lane >> 2, tig = lane & 3;
    const int wm = wid & 1, wn = wid >> 1;
    const int b = blockIdx.z;
    const int p0 = blockIdx.x * 256;
    const int o0 = blockIdx.y * 64;
    const size_t bofs = (size_t)b * NP;

    // A cp.async roles: 2 ops/thread
    uint32_t aSm[2];
    const __nv_bfloat16* aGp[2];
#pragma unroll
    for (int r = 0; r < 2; r++) {
        int idx = r * 256 + tid, plane = idx >> 8, rem = idx & 255;
        int row = rem >> 2, c16 = rem & 3;
        aSm[r] = plane * PL_A + row * SMA_ROW + c16 * 16;
        aGp[r] = (plane ? g_wlo : g_whi) + wOff + (size_t)(o0 + row) * K + c16 * 8;
    }
    // B cp.async roles: 8 ops/thread
    uint32_t bSm[8];
    int bKrow[8], bPlane[8], bCol[8];
#pragma unroll
    for (int r = 0; r < 8; r++) {
        int idx = r * 256 + tid, plane = idx >> 10, rem = idx & 1023;
        int krow = rem >> 5, c16 = rem & 31;
        bSm[r] = SOFF_B + plane * PL_B + krow * SMB_ROW + c16 * 16;
        bKrow[r] = krow; bPlane[r] = plane; bCol[r] = p0 + c16 * 8;
    }

    auto issue = [&](int kc, int buf) {
        uint32_t base = sb + buf * BUFSZ;
#pragma unroll
        for (int r = 0; r < 2; r++)
            cpasync16(base + aSm[r], aGp[r] + kc);
#pragma unroll
        for (int r = 0; r < 8; r++) {
            int kg = kc + bKrow[r];
            size_t ch = (kg < K1) ? (aOff1 + kg) : (aOff2 + (kg - K1));
            const __nv_bfloat16* src = (bPlane[r] ? g_lo : g_hi)
                                     + ch * (size_t)PL + bofs + bCol[r];
            cpasync16(base + bSm[r], src);
        }
        CP_COMMIT();
    };

    // ldmatrix lane offsets
    const uint32_t offAt = (uint32_t)(lane & 15) * SMA_ROW + (uint32_t)(lane >> 4) * 16
                         + (uint32_t)(wm * 32) * SMA_ROW;
    const uint32_t offBt = (uint32_t)((lane & 7) + ((lane >> 3) & 1) * 8) * SMB_ROW
                         + (uint32_t)(lane >> 4) * 16;

    float acc[2][8][4];
#pragma unroll
    for (int i = 0; i < 2; i++)
#pragma unroll
        for (int j = 0; j < 8; j++)
#pragma unroll
            for (int q = 0; q < 4; q++) acc[i][j][q] = 0.f;

    const int nch = K >> 5;
    issue(0, 0);
    CP_WAIT0();
    __syncthreads();

    for (int c = 0; c < nch; c++) {
        const bool more = (c + 1 < nch);
        if (more) issue((c + 1) * 32, (c + 1) & 1);

        uint32_t base = sb + (c & 1) * BUFSZ;
        uint32_t aH = base + offAt, aL = aH + PL_A;
        uint32_t bH = base + SOFF_B + offBt, bL = bH + PL_B;
#pragma unroll
        for (int s = 0; s < 2; s++) {
            uint32_t ah[2][4], al[2][4];
#pragma unroll
            for (int i = 0; i < 2; i++) {
                ldsm4(ah[i], aH + i * (16 * SMA_ROW) + s * 32);
                ldsm4(al[i], aL + i * (16 * SMA_ROW) + s * 32);
            }
#pragma unroll
            for (int t = 0; t < 4; t++) {
                uint32_t bh4[4], bl4[4];
                uint32_t bo = s * (16 * SMB_ROW) + (uint32_t)(wn * 64 + t * 16) * 2;
                ldsm4t(bh4, bH + bo);
                ldsm4t(bl4, bL + bo);
#pragma unroll
                for (int jj = 0; jj < 2; jj++) {
                    int j = t * 2 + jj;
                    const uint32_t* bhf = &bh4[jj * 2];
                    const uint32_t* blf = &bl4[jj * 2];
#pragma unroll
                    for (int i = 0; i < 2; i++) {
                        mma16816(acc[i][j], ah[i], bhf);
                        mma16816(acc[i][j], al[i], bhf);
                        mma16816(acc[i][j], ah[i], blf);
                    }
                }
            }
        }
        if (more) CP_WAIT0();
        __syncthreads();
    }

    // ---- epilogue ----
    const int obase = o0 + wm * 32;
    const int pbase = p0 + wn * 64;

    auto rd2 = [&](size_t ch, int o, int p, float& v0, float& v1) {
        size_t ix = (ch + o) * (size_t)PL + bofs + p;
        uint32_t hu = *(const uint32_t*)(g_hi + ix);
        uint32_t lu = *(const uint32_t*)(g_lo + ix);
        v0 = __uint_as_float(hu << 16) + __uint_as_float(lu << 16);
        v1 = __uint_as_float(hu & 0xffff0000u) + __uint_as_float(lu & 0xffff0000u);
    };
    auto emit = [&](int o, int p, float d0, float d1) {
        float y0, y1;
        if (mode == 0) { y0 = d0; y1 = d1; }
        else if (mode == 1) {
            float e0, e1v; rd2(e1Off, o, p, e0, e1v);
            y0 = d0 + e0; y1 = d1 + e1v;
        } else if (mode == 2) {
            float b0, b1;
            if (o < Chalf) rd2(e1Off, o, p, b0, b1);
            else           rd2(e2Off, o - Chalf, p, b0, b1);
            y0 = d0 * b0 + b0; y1 = d1 * b1 + b1;
        } else {
            float r0, r1, x0, x1;
            rd2(e1Off, o, p, r0, r1);
            rd2(e2Off, o, p, x0, x1);
            r0 += d0; r1 += d1;
            float g0 = 0.5f * x0 * (1.f + erff(x0 * 0.70710678118654752f));
            float g1 = 0.5f * x1 * (1.f + erff(x1 * 0.70710678118654752f));
            y0 = g0 * r0; y1 = g1 * r1;
        }
        if (Yf) {
            *(float2*)(Yf + ((size_t)b * Cout + o) * NP + p) = make_float2(y0, y1);
        } else {
            uint32_t hp, lp; hilo2(y0, y1, hp, lp);
            size_t ix = (yOff + o) * (size_t)PL + bofs + p;
            *(uint32_t*)(g_hi + ix) = hp;
            *(uint32_t*)(g_lo + ix) = lp;
        }
    };

#pragma unroll
    for (int i = 0; i < 2; i++) {
#pragma unroll
        for (int j = 0; j < 8; j++) {
            int oA = obase + i * 16 + g;
            int p  = pbase + j * 8 + tig * 2;
            emit(oA,     p, acc[i][j][0], acc[i][j][1]);
            emit(oA + 8, p, acc[i][j][2], acc[i][j][3]);
        }
    }
}

// ---------------- LayerNorm (fp32 in -> hl out) ----------------
__global__ void ln_f32(const float* __restrict__ in, const float* __restrict__ g,
                       const float* __restrict__ be, size_t dstCh)
{
    int b = blockIdx.y;
    int p = blockIdx.x * 256 + threadIdx.x;
    const float* ib = in + (size_t)b * 192 * NP + p;
    float s = 0.f, ss = 0.f;
    for (int c = 0; c < 192; c++) {
        float v = ib[(size_t)c * NP];
        s += v; ss += v * v;
    }
    float mu = s / 192.f;
    float var = ss / 192.f - mu * mu;
    float rstd = rsqrtf(var + 1e-5f);
    size_t ob = dstCh * (size_t)PL + (size_t)b * NP + p;
    for (int c = 0; c < 192; c++) {
        float v = ib[(size_t)c * NP];
        wrhl(ob + (size_t)c * PL, (v - mu) * rstd * g[c] + be[c]);
    }
}
// ---------------- LayerNorm (hl in -> hl out) ----------------
__global__ void ln_hl(size_t srcCh, const float* __restrict__ g,
                      const float* __restrict__ be, size_t dstCh)
{
    int b = blockIdx.y;
    int p = blockIdx.x * 256 + threadIdx.x;
    size_t ibase = srcCh * (size_t)PL + (size_t)b * NP + p;
    float s = 0.f, ss = 0.f;
    for (int c = 0; c < 192; c++) {
        float v = rdhl(ibase + (size_t)c * PL);
        s += v; ss += v * v;
    }
    float mu = s / 192.f;
    float var = ss / 192.f - mu * mu;
    float rstd = rsqrtf(var + 1e-5f);
    size_t ob = dstCh * (size_t)PL + (size_t)b * NP + p;
    for (int c = 0; c < 192; c++) {
        float v = rdhl(ibase + (size_t)c * PL);
        wrhl(ob + (size_t)c * PL, (v - mu) * rstd * g[c] + be[c]);
    }
}

// ---------------- depthwise 3x3 (hl -> hl) ----------------
__global__ void dw_hl(size_t srcCh, const float* __restrict__ w, size_t dstCh, int C)
{
    int b = blockIdx.z, c = blockIdx.y;
    int p = blockIdx.x * 256 + threadIdx.x;
    int y = p >> 7, x = p & 127;
    size_t ib = (srcCh + c) * (size_t)PL + (size_t)b * NP;
    const float* wc = w + c * 9;
    float acc = 0.f;
#pragma unroll
    for (int dy = -1; dy <= 1; dy++) {
        int yy = y + dy;
        if (yy < 0 || yy > 127) continue;
#pragma unroll
        for (int dx = -1; dx <= 1; dx++) {
            int xx = x + dx;
            if (xx < 0 || xx > 127) continue;
            acc = fmaf(rdhl(ib + yy * 128 + xx), wc[(dy + 1) * 3 + (dx + 1)], acc);
        }
    }
    wrhl((dstCh + c) * (size_t)PL + (size_t)b * NP + p, acc);
}

// ---------------- row L2 norms of q,k ----------------
__global__ void norm_kernel(float* __restrict__ nrm)
{
    int r = blockIdx.x;              // 0..767
    int b = r / 384, c = r % 384;
    size_t src = (CH_QKV + c) * (size_t)PL + (size_t)b * NP;
    float s = 0.f;
    for (int i = threadIdx.x; i < NP; i += 256) {
        float v = rdhl(src + i);
        s += v * v;
    }
    __shared__ float red[256];
    red[threadIdx.x] = s;
    __syncthreads();
    for (int st = 128; st > 0; st >>= 1) {
        if (threadIdx.x < st) red[threadIdx.x] += red[threadIdx.x + st];
        __syncthreads();
    }
    if (threadIdx.x == 0) nrm[r] = fmaxf(sqrtf(red[0]), 1e-12f);
}

// ---------------- attention scores ----------------
__global__ void scores_kernel(float* __restrict__ S)
{
    int bh = blockIdx.x;
    int ks = blockIdx.y;
    int b = bh / 6, h = bh % 6;
    size_t qb = (CH_QKV + h * 32) * (size_t)PL + (size_t)b * NP;
    size_t kb = (CH_QKV + 192 + h * 32) * (size_t)PL + (size_t)b * NP;
    __shared__ float qs[32][65], ksm[32][65];
    int tid = threadIdx.x;
    int c = tid >> 3, d0 = (tid & 7) * 4;
    float acc[4] = {0.f, 0.f, 0.f, 0.f};
    int kbase = ks * (NP / KSPLIT);
    for (int t = 0; t < (NP / KSPLIT) / 64; t++) {
        int k0 = kbase + t * 64;
#pragma unroll
        for (int i = 0; i < 8; i++) {
            int e = tid + i * 256;
            int row = e >> 6, col = e & 63;
            qs[row][col]  = rdhl(qb + (size_t)row * PL + k0 + col);
            ksm[row][col] = rdhl(kb + (size_t)row * PL + k0 + col);
        }
        __syncthreads();
#pragma unroll
        for (int kk = 0; kk < 64; kk++) {
            float qv = qs[c][kk];
#pragma unroll
            for (int j = 0; j < 4; j++)
                acc[j] = fmaf(qv, ksm[d0 + j][kk], acc[j]);
        }
        __syncthreads();
    }
    float* Sp = S + (size_t)ks * 12288 + bh * 1024 + c * 32 + d0;
#pragma unroll
    for (int j = 0; j < 4; j++) Sp[j] = acc[j];
}

// ---------------- softmax with norm + temperature ----------------
__global__ void softmax_kernel(float* __restrict__ S, const float* __restrict__ nrm,
                               const float* __restrict__ temp)
{
    int bh = blockIdx.y;
    int c  = blockIdx.x;
    int b = bh / 6, h = bh % 6;
    int d = threadIdx.x;
    float acc = 0.f;
    size_t idx = (size_t)bh * 1024 + c * 32 + d;
    for (int j = 0; j < KSPLIT; j++) acc += S[(size_t)j * 12288 + idx];
    float nq = nrm[b * 384 + h * 32 + c];
    float nk = nrm[b * 384 + 192 + h * 32 + d];
    float v = acc / (nq * nk) * temp[h];
    float m = v;
    for (int o = 16; o; o >>= 1) m = fmaxf(m, __shfl_xor_sync(0xffffffffu, m, o));
    float e = expf(v - m);
    float s = e;
    for (int o = 16; o; o >>= 1) s += __shfl_xor_sync(0xffffffffu, s, o);
    S[idx] = e / s;
}

// ---------------- out = attn @ v (hl in, hl out) ----------------
__global__ void av_kernel(const float* __restrict__ S)
{
    int b = blockIdx.z, h = blockIdx.y;
    int p = blockIdx.x * 128 + threadIdx.x;
    __shared__ float A[32][32];
    int bh = b * 6 + h;
    for (int i = threadIdx.x; i < 1024; i += 128)
        A[i >> 5][i & 31] = S[(size_t)bh * 1024 + i];
    __syncthreads();
    size_t vb = (CH_QKV + 384 + h * 32) * (size_t)PL + (size_t)b * NP + p;
    float vr[32];
#pragma unroll
    for (int d = 0; d < 32; d++) vr[d] = rdhl(vb + (size_t)d * PL);
    size_t ob = (CH_OUTA + h * 32) * (size_t)PL + (size_t)b * NP + p;
#pragma unroll
    for (int c = 0; c < 32; c++) {
        float acc = 0.f;
#pragma unroll
        for (int d = 0; d < 32; d++) acc = fmaf(A[c][d], vr[d], acc);
        wrhl(ob + (size_t)c * PL, acc);
    }
}

// ---------------- host orchestration ----------------
static inline void launch_gemm(size_t wOff, int K, size_t aOff1, int K1, size_t aOff2,
                               int Cout, size_t e1Off, size_t e2Off, size_t yOff,
                               int mode, int Chalf, float* Yf)
{
    dim3 grid(NP / 256, Cout / 64, NB);
    hmma_gemm<<<grid, 256, GSMEM>>>(wOff, K, aOff1, K1, aOff2, Cout,
                                    e1Off, e2Off, yOff, mode, Chalf, Yf);
}

extern "C" void kernel_launch(void* const* d_in, const int* in_sizes, int n_in,
                              void* d_out, int out_size)
{
    const float* x       = (const float*)d_in[0];
    const float* feature = (const float*)d_in[1];
    const float* nf_w = (const float*)d_in[2];
    const float* nf_b = (const float*)d_in[3];
    const float* n1_w = (const float*)d_in[4];
    const float* n1_b = (const float*)d_in[5];
    const float* n2_w = (const float*)d_in[6];
    const float* n2_b = (const float*)d_in[7];
    const float* a_cc_w   = (const float*)d_in[8];
    const float* a_fus_w  = (const float*)d_in[9];
    const float* a_msk_w  = (const float*)d_in[10];
    const float* a_qkv_w  = (const float*)d_in[11];
    const float* a_qkvdw  = (const float*)d_in[12];
    const float* a_temp   = (const float*)d_in[13];
    const float* a_proj_w = (const float*)d_in[14];
    const float* f_pm_w   = (const float*)d_in[15];
    const float* f_pi_w   = (const float*)d_in[16];
    const float* f_dw_w   = (const float*)d_in[17];
    const float* f_cc_w   = (const float*)d_in[18];
    const float* f_fus_w  = (const float*)d_in[19];
    const float* f_msk_w  = (const float*)d_in[20];
    const float* f_po_w   = (const float*)d_in[21];
    float* out = (float*)d_out;

    cudaFuncSetAttribute(hmma_gemm, cudaFuncAttributeMaxDynamicSharedMemorySize, GSMEM);

    float* f32 = nullptr;
    cudaGetSymbolAddress((void**)&f32, g_f32);
    float* NRM = f32;
    float* S   = f32 + 1024;

    // ---- weight + x conversion ----
    auto cw = [&](const float* src, size_t off, int n) {
        cvt_w<<<(n + 255) / 256, 256>>>(src, off, n);
    };
    cw(a_msk_w,  WO_AMSK,  36864);
    cw(a_cc_w,   WO_ACC,   147456);
    cw(a_fus_w,  WO_AFUS,  73728);
    cw(a_qkv_w,  WO_AQKV,  110592);
    cw(a_proj_w, WO_APROJ, 36864);
    cw(f_pm_w,   WO_FPM,   110592);
    cw(f_pi_w,   WO_FPI,   221184);
    cw(f_msk_w,  WO_FMSK,  331776);
    cw(f_cc_w,   WO_FCC,   1327104);
    cw(f_fus_w,  WO_FFUS,  663552);
    cw(f_po_w,   WO_FPO,   110592);
    cvt_act<<<dim3(NP / 256, 192, NB), 256>>>(x, 192, CH_X);

    dim3 lng(NP / 256, NB);
    ln_f32<<<lng, 256>>>(feature, nf_w, nf_b, CH_F);
    ln_f32<<<lng, 256>>>(x, n1_w, n1_b, CH_X1);

    // --- attention DDF ---
    launch_gemm(WO_AMSK, 192, CH_F, 192, CH_F, 192, 0, 0, CH_MT, 0, 0, nullptr);
    launch_gemm(WO_ACC, 384, CH_X1, 192, CH_MT, 384, CH_X1, CH_MT, CH_OUTD, 2, 192, nullptr);
    launch_gemm(WO_AFUS, 384, CH_OUTD, 384, CH_OUTD, 192, CH_X1, 0, CH_ATTIN, 1, 0, nullptr);

    // qkv + depthwise
    launch_gemm(WO_AQKV, 192, CH_ATTIN, 192, CH_ATTIN, 576, 0, 0, CH_QKV0, 0, 0, nullptr);
    dw_hl<<<dim3(NP / 256, 576, NB), 256>>>(CH_QKV0, a_qkvdw, CH_QKV, 576);

    // channel attention
    norm_kernel<<<768, 256>>>(NRM);
    scores_kernel<<<dim3(12, KSPLIT), 256>>>(S);
    softmax_kernel<<<dim3(32, 12), 32>>>(S, NRM, a_temp);
    av_kernel<<<dim3(NP / 128, 6, NB), 128>>>(S);

    // proj + residual with original x
    launch_gemm(WO_APROJ, 192, CH_OUTA, 192, CH_OUTA, 192, CH_X, 0, CH_XMID, 1, 0, nullptr);

    // --- FFN ---
    ln_hl<<<lng, 256>>>(CH_XMID, n2_w, n2_b, CH_X2L);
    launch_gemm(WO_FPM, 192, CH_F, 192, CH_F, 576, 0, 0, CH_FM, 0, 0, nullptr);
    launch_gemm(WO_FPI, 192, CH_X2L, 192, CH_X2L, 1152, 0, 0, CH_XIN, 0, 0, nullptr);
    dw_hl<<<dim3(NP / 256, 1152, NB), 256>>>(CH_XIN, f_dw_w, CH_DW, 1152);

    launch_gemm(WO_FMSK, 576, CH_FM, 576, CH_FM, 576, 0, 0, CH_MT2, 0, 0, nullptr);
    launch_gemm(WO_FCC, 1152, CH_X2H, 576, CH_MT2, 1152, CH_X2H, CH_MT2, CH_OUT2, 2, 576, nullptr);
    launch_gemm(WO_FFUS, 1152, CH_OUT2, 1152, CH_OUT2, 576, CH_X2H, CH_DW, CH_GX, 3, 0, nullptr);
    launch_gemm(WO_FPO, 576, CH_GX, 576, CH_GX, 192, CH_XMID, 0, 0, 1, 0, out);
}